// round 15
// baseline (speedup 1.0000x reference)
#include <cuda_runtime.h>
#include <cuda_bf16.h>
#include <math.h>
#include <stdint.h>

// ---------------- Problem constants ----------------
#define BB      8
#define SEQLEN  4096
#define CINC    7
#define DMOD    512
#define NLAY    4
#define PLEN    16
#define NPATCH  256
#define NST     16
#define DCONV   4
#define DINNER  1024
#define DTRANK  32
#define MROWS   (BB*NPATCH)    // 2048
#define KPATCH  112
#define KPPAD   128
#define HPRED   96
#define HKS     256
#define KFLAT   (NPATCH*DMOD)  // 131072
#define DBLKS   4

// ---------------- fp32 scratch ----------------
__device__ float g_h   [MROWS*DMOD];
__device__ float g_ln  [MROWS*DMOD];
__device__ float g_xz  [MROWS*2*DINNER];
__device__ float g_dblp[DBLKS*MROWS*64];
__device__ float g_part[HKS*BB*128];

// ---------------- bf16 hi/lo activation planes ----------------
__device__ __nv_bfloat16 g_pnh[MROWS*KPPAD],  g_pnl[MROWS*KPPAD];
__device__ __nv_bfloat16 g_lnh[MROWS*DMOD],   g_lnl[MROWS*DMOD];
__device__ __nv_bfloat16 g_yh [MROWS*DINNER], g_yl [MROWS*DINNER];

// ---------------- bf16 hi/lo weight planes ----------------
__device__ __nv_bfloat16 g_peWh[DMOD*KPPAD],         g_peWl[DMOD*KPPAD];
__device__ __nv_bfloat16 g_Winh[NLAY*2*DINNER*DMOD], g_Winl[NLAY*2*DINNER*DMOD];
__device__ __nv_bfloat16 g_Wxh [NLAY*64*DINNER],     g_Wxl [NLAY*64*DINNER];
__device__ __nv_bfloat16 g_Wouth[NLAY*DMOD*DINNER],  g_Woutl[NLAY*DMOD*DINNER];

#define NWIN  (NLAY*2*DINNER*DMOD)
#define NWOUT (NLAY*DMOD*DINNER)
#define NWX   (NLAY*64*DINNER)

// =====================================================================
// Helpers
// =====================================================================
static __device__ __forceinline__ uint32_t smem_u32(const void* p) {
    uint32_t a;
    asm("{ .reg .u64 t; cvta.to.shared.u64 t, %1; cvt.u32.u64 %0, t; }"
        : "=r"(a) : "l"(p));
    return a;
}
static __device__ __forceinline__ void ldm_x4(uint32_t* r, uint32_t addr) {
    asm volatile("ldmatrix.sync.aligned.m8n8.x4.shared.b16 {%0,%1,%2,%3}, [%4];"
        : "=r"(r[0]), "=r"(r[1]), "=r"(r[2]), "=r"(r[3]) : "r"(addr));
}
static __device__ __forceinline__ void mma_bf16(float* c, const uint32_t* a,
                                                const uint32_t* b) {
    asm volatile(
        "mma.sync.aligned.m16n8k16.row.col.f32.bf16.bf16.f32 "
        "{%0,%1,%2,%3}, {%4,%5,%6,%7}, {%8,%9}, {%0,%1,%2,%3};"
        : "+f"(c[0]), "+f"(c[1]), "+f"(c[2]), "+f"(c[3])
        : "r"(a[0]), "r"(a[1]), "r"(a[2]), "r"(a[3]), "r"(b[0]), "r"(b[1]));
}
static __device__ __forceinline__ void cp16(uint32_t dst, const void* src) {
    asm volatile("cp.async.cg.shared.global [%0], [%1], 16;"
                 :: "r"(dst), "l"(src));
}
static __device__ __forceinline__ void cp_commit() {
    asm volatile("cp.async.commit_group;");
}
template<int NW> static __device__ __forceinline__ void cp_wait() {
    asm volatile("cp.async.wait_group %0;" :: "n"(NW));
}
static __device__ __forceinline__ void split1(float v, __nv_bfloat16& h, __nv_bfloat16& l) {
    h = __float2bfloat16(v);
    l = __float2bfloat16(v - __bfloat162float(h));
}
static __device__ __forceinline__ uint32_t pk2(__nv_bfloat16 a, __nv_bfloat16 b) {
    return (uint32_t)__bfloat16_as_ushort(a) | ((uint32_t)__bfloat16_as_ushort(b) << 16);
}
static __device__ __forceinline__ void split4v(float4 v, uint2& h, uint2& l) {
    __nv_bfloat16 h0,l0,h1,l1,h2,l2,h3,l3;
    split1(v.x,h0,l0); split1(v.y,h1,l1); split1(v.z,h2,l2); split1(v.w,h3,l3);
    h = make_uint2(pk2(h0,h1), pk2(h2,h3));
    l = make_uint2(pk2(l0,l1), pk2(l2,l3));
}
static __device__ __forceinline__ uint32_t swz64(int row, int u) {
    return (uint32_t)(row * 64 + ((u ^ ((row >> 1) & 3)) << 4));
}
// byte-granular swizzled offset within a 64B-row plane
static __device__ __forceinline__ uint32_t swzb(int row, int byteoff) {
    return (uint32_t)(row * 64 + ((((byteoff >> 4) ^ ((row >> 1) & 3)) << 4)
                                 | (byteoff & 15)));
}

// =====================================================================
// Fused prep: weight split + input patchnorm in ONE launch
// =====================================================================
__global__ void __launch_bounds__(256)
k_prep(const float* __restrict__ peW, const float* __restrict__ Win,
       const float* __restrict__ Wx,  const float* __restrict__ Wout,
       const float* __restrict__ x,   const float* __restrict__ in_g,
       const float* __restrict__ in_b)
{
    const int t0 = blockIdx.x * blockDim.x + threadIdx.x;
    const int stride = gridDim.x * blockDim.x;
    constexpr int T1 = NWIN / 4;
    constexpr int T2 = T1 + NWOUT / 4;
    constexpr int T3 = T2 + NWX / 4;

    for (int i4 = t0; i4 < T3; i4 += stride) {
        const float* src; __nv_bfloat16 *dh, *dl; int off;
        if (i4 < T1)      { src = Win;  dh = g_Winh;  dl = g_Winl;  off = i4; }
        else if (i4 < T2) { src = Wout; dh = g_Wouth; dl = g_Woutl; off = i4 - T1; }
        else              { src = Wx;   dh = g_Wxh;   dl = g_Wxl;   off = i4 - T2; }
        float4 v = *(const float4*)&src[(size_t)off * 4];
        uint2 h, l; split4v(v, h, l);
        *(uint2*)&dh[(size_t)off * 4] = h;
        *(uint2*)&dl[(size_t)off * 4] = l;
    }
    for (int i4 = t0; i4 < DMOD * (KPATCH / 4); i4 += stride) {
        int r = i4 / (KPATCH / 4), c4 = i4 % (KPATCH / 4);
        float4 v = *(const float4*)&peW[(size_t)r * KPATCH + c4 * 4];
        uint2 h, l; split4v(v, h, l);
        *(uint2*)&g_peWh[(size_t)r * KPPAD + c4 * 4] = h;
        *(uint2*)&g_peWl[(size_t)r * KPPAD + c4 * 4] = l;
    }
    for (int idx = t0; idx < BB * SEQLEN; idx += stride) {
        int b = idx / SEQLEN, s = idx % SEQLEN;
        const float* xp = x + idx * CINC;
        float sum = 0.f;
        #pragma unroll
        for (int c = 0; c < CINC; c++) sum += xp[c];
        float m = sum * (1.f / CINC);
        float var = 0.f;
        #pragma unroll
        for (int c = 0; c < CINC; c++) { float d = xp[c] - m; var = fmaf(d, d, var); }
        var *= (1.f / CINC);
        float inv = rsqrtf(var + 1e-5f);
        int n = s / PLEN, p = s % PLEN;
        size_t ro = (size_t)(b * NPATCH + n) * KPPAD;
        #pragma unroll
        for (int c = 0; c < CINC; c++) {
            float v = (xp[c] - m) * inv * in_g[c] + in_b[c];
            __nv_bfloat16 h, l; split1(v, h, l);
            g_pnh[ro + c * PLEN + p] = h;
            g_pnl[ro + c * PLEN + p] = l;
        }
    }
}

// =====================================================================
// bf16x3 mma.sync GEMM: swizzled SMEM, 3-stage cp.async.
// EPI: 0=store, 1=store+bias[n], 2=accumulate into C
// =====================================================================
template<int BM, int BN, int EPI>
__global__ void __launch_bounds__(256, 2)
bgemm(int M, int N, int Ks,
      const __nv_bfloat16* __restrict__ Ah, const __nv_bfloat16* __restrict__ Al, int lda,
      const __nv_bfloat16* __restrict__ Wh, const __nv_bfloat16* __restrict__ Wl, int ldw,
      const float* __restrict__ bias, float* __restrict__ C, int ldc, int sliceC)
{
    constexpr int WNW = (BM == 128) ? 2 : 4;
    constexpr int WN  = BN / WNW;
    constexpr int NT8 = WN / 8;
    constexpr int APLB = BM * 64;
    constexpr int WPLB = BN * 64;
    constexpr int STGB = 2 * APLB + 2 * WPLB;

    extern __shared__ __nv_bfloat16 sm[];
    const uint32_t smu = smem_u32(sm);

    const int tid = threadIdx.x, lane = tid & 31, warp = tid >> 5;
    const int wn = warp % WNW, wm = warp / WNW;
    const int mB = blockIdx.y * BM, nB = blockIdx.x * BN;
    const int kbase = blockIdx.z * Ks;
    float* pC = C + (size_t)blockIdx.z * sliceC;

    float acc[2][NT8][4];
    #pragma unroll
    for (int t = 0; t < 2; t++)
        #pragma unroll
        for (int j = 0; j < NT8; j++)
            #pragma unroll
            for (int r = 0; r < 4; r++) acc[t][j][r] = 0.f;

    const int nCh = Ks / 32;

    auto load_stage = [&](int s) {
        const uint32_t sb = smu + (uint32_t)((s % 3) * STGB);
        const int k0 = kbase + s * 32;
        #pragma unroll
        for (int i = tid; i < BM * 4; i += 256) {
            int row = i >> 2, u = i & 3;
            size_t g = (size_t)(mB + row) * lda + k0 + u * 8;
            uint32_t d = sb + swz64(row, u);
            cp16(d, Ah + g);
            cp16(d + APLB, Al + g);
        }
        #pragma unroll
        for (int i = tid; i < BN * 4; i += 256) {
            int row = i >> 2, u = i & 3;
            size_t g = (size_t)(nB + row) * ldw + k0 + u * 8;
            uint32_t d = sb + 2 * APLB + swz64(row, u);
            cp16(d, Wh + g);
            cp16(d + WPLB, Wl + g);
        }
        cp_commit();
    };

    load_stage(0);
    if (nCh > 1) load_stage(1); else cp_commit();

    for (int s = 0; s < nCh; s++) {
        if (s + 2 < nCh) load_stage(s + 2); else cp_commit();
        cp_wait<2>();
        __syncthreads();

        const uint32_t sb = smu + (uint32_t)((s % 3) * STGB);
        #pragma unroll
        for (int k16 = 0; k16 < 2; k16++) {
            uint32_t ah[2][4], al[2][4], wf[NT8][2];
            const int arow = wm * 32 + (lane & 15);
            const int au   = k16 * 2 + (lane >> 4);
            const uint32_t aAddr = sb + swz64(arow, au);
            ldm_x4(ah[0], aAddr);
            ldm_x4(ah[1], aAddr + 16 * 64);

            const int wrow = wn * WN + ((lane >> 4) << 3) + (lane & 7);
            const int wu   = k16 * 2 + ((lane >> 3) & 1);
            const uint32_t wAddr = sb + 2 * APLB + swz64(wrow, wu);
            #pragma unroll
            for (int jp = 0; jp < NT8 / 2; jp++) {
                uint32_t t4[4];
                ldm_x4(t4, wAddr + jp * 16 * 64);
                wf[2*jp][0] = t4[0]; wf[2*jp][1] = t4[1];
                wf[2*jp+1][0] = t4[2]; wf[2*jp+1][1] = t4[3];
            }
            #pragma unroll
            for (int t = 0; t < 2; t++)
                #pragma unroll
                for (int j = 0; j < NT8; j++) mma_bf16(acc[t][j], ah[t], wf[j]);

            ldm_x4(al[0], aAddr + APLB);
            ldm_x4(al[1], aAddr + APLB + 16 * 64);
            #pragma unroll
            for (int t = 0; t < 2; t++)
                #pragma unroll
                for (int j = 0; j < NT8; j++) mma_bf16(acc[t][j], al[t], wf[j]);

            #pragma unroll
            for (int jp = 0; jp < NT8 / 2; jp++) {
                uint32_t t4[4];
                ldm_x4(t4, wAddr + WPLB + jp * 16 * 64);
                wf[2*jp][0] = t4[0]; wf[2*jp][1] = t4[1];
                wf[2*jp+1][0] = t4[2]; wf[2*jp+1][1] = t4[3];
            }
            #pragma unroll
            for (int t = 0; t < 2; t++)
                #pragma unroll
                for (int j = 0; j < NT8; j++) mma_bf16(acc[t][j], ah[t], wf[j]);
        }
        __syncthreads();
    }

    #pragma unroll
    for (int t = 0; t < 2; t++) {
        const int m = mB + wm * 32 + t * 16 + (lane >> 2);
        #pragma unroll
        for (int j = 0; j < NT8; j++) {
            const int n = nB + wn * WN + j * 8 + (lane & 3) * 2;
            float2 v0 = make_float2(acc[t][j][0], acc[t][j][1]);
            float2 v1 = make_float2(acc[t][j][2], acc[t][j][3]);
            if (EPI == 1) {
                float b0 = bias[n], b1 = bias[n + 1];
                v0.x += b0; v0.y += b1; v1.x += b0; v1.y += b1;
            }
            if (EPI == 2) {
                float2 p0 = *(const float2*)&pC[(size_t)m * ldc + n];
                float2 p1 = *(const float2*)&pC[(size_t)(m + 8) * ldc + n];
                v0.x += p0.x; v0.y += p0.y; v1.x += p1.x; v1.y += p1.y;
            }
            *(float2*)&pC[(size_t)m * ldc + n]       = v0;
            *(float2*)&pC[(size_t)(m + 8) * ldc + n] = v1;
        }
    }
}

// =====================================================================
// dbl GEMM with INLINE conv+silu A-operand (fuses k_conv + dbl bgemm).
// A[row, d] = silu(causal_conv4(xz_xi)[row, d]); W = Wx planes (cp.async).
// Tile 64 x 64, Ks = DINNER/DBLKS per z-slice, 3-stage ring.
// =====================================================================
__global__ void __launch_bounds__(256, 2)
dgemm_conv(const float* __restrict__ xz,
           const float* __restrict__ cw, const float* __restrict__ cb,
           const __nv_bfloat16* __restrict__ Wh, const __nv_bfloat16* __restrict__ Wl,
           float* __restrict__ C)
{
    constexpr int BM = 64, BN = 64;
    constexpr int WNW = 4, WN = BN / WNW, NT8 = WN / 8;
    constexpr int APLB = BM * 64;
    constexpr int WPLB = BN * 64;
    constexpr int STGB = 2 * APLB + 2 * WPLB;   // 16384 B
    const int Ks = DINNER / DBLKS;              // 256

    extern __shared__ __nv_bfloat16 sm[];
    const uint32_t smu = smem_u32(sm);
    char* smc = (char*)sm;

    const int tid = threadIdx.x, lane = tid & 31, warp = tid >> 5;
    const int wn = warp % WNW, wm = warp / WNW;
    const int mB = blockIdx.y * BM;
    const int kbase = blockIdx.z * Ks;
    float* pC = C + (size_t)blockIdx.z * (MROWS * 64);

    float acc[2][NT8][4];
    #pragma unroll
    for (int t = 0; t < 2; t++)
        #pragma unroll
        for (int j = 0; j < NT8; j++)
            #pragma unroll
            for (int r = 0; r < 4; r++) acc[t][j][r] = 0.f;

    const int nCh = Ks / 32;    // 8

    auto load_stage = [&](int s) {
        const int sb3 = (s % 3) * STGB;
        const uint32_t sb = smu + (uint32_t)sb3;
        const int k0 = kbase + s * 32;
        // A: compute conv+silu inline, store swizzled (hi/lo planes)
        #pragma unroll
        for (int i = tid; i < BM * 16; i += 256) {   // 1024 items: row x dpair
            int row = i >> 4, dp = i & 15;
            int bl = mB + row;
            int l  = bl & (NPATCH - 1);
            int d0 = k0 + dp * 2;
            float vv[2];
            #pragma unroll
            for (int e = 0; e < 2; e++) {
                int d = d0 + e;
                float4 w = *(const float4*)(cw + d * 4);
                float a = cb[d];
                size_t base = (size_t)bl * 2 * DINNER + d;
                if (l >= 3) a = fmaf(xz[base - 3 * 2 * DINNER], w.x, a);
                if (l >= 2) a = fmaf(xz[base - 2 * 2 * DINNER], w.y, a);
                if (l >= 1) a = fmaf(xz[base - 1 * 2 * DINNER], w.z, a);
                a = fmaf(xz[base], w.w, a);
                vv[e] = a / (1.f + __expf(-a));
            }
            __nv_bfloat16 h0, l0, h1, l1;
            split1(vv[0], h0, l0); split1(vv[1], h1, l1);
            uint32_t off = swzb(row, dp * 4);
            *(uint32_t*)(smc + sb3 + off)        = pk2(h0, h1);
            *(uint32_t*)(smc + sb3 + APLB + off) = pk2(l0, l1);
        }
        // W: cp.async from pre-split planes
        #pragma unroll
        for (int i = tid; i < BN * 4; i += 256) {
            int row = i >> 2, u = i & 3;
            size_t g = (size_t)row * DINNER + k0 + u * 8;
            uint32_t d = sb + 2 * APLB + swz64(row, u);
            cp16(d, Wh + g);
            cp16(d + WPLB, Wl + g);
        }
        cp_commit();
    };

    load_stage(0);
    load_stage(1);

    for (int s = 0; s < nCh; s++) {
        if (s + 2 < nCh) load_stage(s + 2); else cp_commit();
        cp_wait<2>();
        __syncthreads();

        const uint32_t sb = smu + (uint32_t)((s % 3) * STGB);
        #pragma unroll
        for (int k16 = 0; k16 < 2; k16++) {
            uint32_t ah[2][4], al[2][4], wf[NT8][2];
            const int arow = wm * 32 + (lane & 15);
            const int au   = k16 * 2 + (lane >> 4);
            const uint32_t aAddr = sb + swz64(arow, au);
            ldm_x4(ah[0], aAddr);
            ldm_x4(ah[1], aAddr + 16 * 64);

            const int wrow = wn * WN + ((lane >> 4) << 3) + (lane & 7);
            const int wu   = k16 * 2 + ((lane >> 3) & 1);
            const uint32_t wAddr = sb + 2 * APLB + swz64(wrow, wu);
            {
                uint32_t t4[4];
                ldm_x4(t4, wAddr);
                wf[0][0] = t4[0]; wf[0][1] = t4[1];
                wf[1][0] = t4[2]; wf[1][1] = t4[3];
            }
            #pragma unroll
            for (int t = 0; t < 2; t++)
                #pragma unroll
                for (int j = 0; j < NT8; j++) mma_bf16(acc[t][j], ah[t], wf[j]);

            ldm_x4(al[0], aAddr + APLB);
            ldm_x4(al[1], aAddr + APLB + 16 * 64);
            #pragma unroll
            for (int t = 0; t < 2; t++)
                #pragma unroll
                for (int j = 0; j < NT8; j++) mma_bf16(acc[t][j], al[t], wf[j]);

            {
                uint32_t t4[4];
                ldm_x4(t4, wAddr + WPLB);
                wf[0][0] = t4[0]; wf[0][1] = t4[1];
                wf[1][0] = t4[2]; wf[1][1] = t4[3];
            }
            #pragma unroll
            for (int t = 0; t < 2; t++)
                #pragma unroll
                for (int j = 0; j < NT8; j++) mma_bf16(acc[t][j], ah[t], wf[j]);
        }
        __syncthreads();
    }

    #pragma unroll
    for (int t = 0; t < 2; t++) {
        const int m = mB + wm * 32 + t * 16 + (lane >> 2);
        #pragma unroll
        for (int j = 0; j < NT8; j++) {
            const int n = wn * WN + j * 8 + (lane & 3) * 2;
            *(float2*)&pC[(size_t)m * 64 + n] =
                make_float2(acc[t][j][0], acc[t][j][1]);
            *(float2*)&pC[(size_t)(m + 8) * 64 + n] =
                make_float2(acc[t][j][2], acc[t][j][3]);
        }
    }
}

// =====================================================================
// Warp-per-row layernorm (width 512). SPLIT=1: bf16 planes; 0: fp32.
// =====================================================================
template<int SPLIT>
__global__ void __launch_bounds__(256)
k_lnw(const float* __restrict__ in, float* __restrict__ outf,
      __nv_bfloat16* __restrict__ oh, __nv_bfloat16* __restrict__ ol,
      const float* __restrict__ gam, const float* __restrict__ bet)
{
    const int row  = blockIdx.x * 8 + (threadIdx.x >> 5);
    const int lane = threadIdx.x & 31;
    const float* x = in + (size_t)row * DMOD;

    float4 v[4];
    float s = 0.f, ss = 0.f;
    #pragma unroll
    for (int i = 0; i < 4; i++) {
        v[i] = *(const float4*)&x[i * 128 + lane * 4];
        s  += v[i].x + v[i].y + v[i].z + v[i].w;
        ss += v[i].x*v[i].x + v[i].y*v[i].y + v[i].z*v[i].z + v[i].w*v[i].w;
    }
    #pragma unroll
    for (int o = 16; o > 0; o >>= 1) {
        s  += __shfl_xor_sync(0xffffffffu, s,  o);
        ss += __shfl_xor_sync(0xffffffffu, ss, o);
    }
    float m   = s * (1.f / DMOD);
    float var = ss * (1.f / DMOD) - m * m;
    float inv = rsqrtf(var + 1e-5f);

    #pragma unroll
    for (int i = 0; i < 4; i++) {
        int c = i * 128 + lane * 4;
        float4 g = *(const float4*)&gam[c];
        float4 bb = *(const float4*)&bet[c];
        float o0 = (v[i].x - m) * inv * g.x + bb.x;
        float o1 = (v[i].y - m) * inv * g.y + bb.y;
        float o2 = (v[i].z - m) * inv * g.z + bb.z;
        float o3 = (v[i].w - m) * inv * g.w + bb.w;
        if (SPLIT) {
            float4 vv = make_float4(o0, o1, o2, o3);
            uint2 h, l; split4v(vv, h, l);
            size_t off = (size_t)row * DMOD + c;
            *(uint2*)&oh[off] = h;
            *(uint2*)&ol[off] = l;
        } else {
            *(float4*)&outf[(size_t)row * DMOD + c] = make_float4(o0, o1, o2, o3);
        }
    }
}

// =====================================================================
// Selective scan: inline conv (running window) + inline delta GEMM +
// fused dbl split-K reduce + gating. 4 lanes per (b,d).
// =====================================================================
__global__ void __launch_bounds__(128)
k_scan(const float* __restrict__ xz,  const float* __restrict__ dblp,
       const float* __restrict__ Wdt, const float* __restrict__ bdt,
       const float* __restrict__ cw,  const float* __restrict__ cb,
       const float* __restrict__ A_log, const float* __restrict__ Dskip)
{
    const int tid  = threadIdx.x;
    const int ng   = tid & 3;
    const int dloc = tid >> 2;
    const int d    = blockIdx.x * 32 + dloc;
    const int b    = blockIdx.y;

    __shared__ float sdbl[16][64];
    __shared__ float swdt[32][33];

    {
        int r = tid >> 2, c0 = (tid & 3) * 8;
        #pragma unroll
        for (int j = 0; j < 8; j++)
            swdt[r][c0 + j] = Wdt[(blockIdx.x * 32 + r) * DTRANK + c0 + j];
    }
    const float bv = bdt[d];
    const float4 cw4 = *(const float4*)(cw + d * 4);
    const float cbv = cb[d];

    float a[4];
    bool structured = true;
    #pragma unroll
    for (int i = 0; i < 4; i++) {
        int n = ng * 4 + i;
        a[i] = -__expf(A_log[d * NST + n]);
        structured = structured && (fabsf(a[i] + (float)(n + 1)) <= 1e-4f * (float)(n + 1));
    }
    const float Dv = Dskip[d];
    float h[4] = {0.f, 0.f, 0.f, 0.f};
    float x1 = 0.f, x2 = 0.f, x3 = 0.f;     // conv window: xi_{t-1}, t-2, t-3

    for (int tt = 0; tt < NPATCH; tt += 16) {
        __syncthreads();
        #pragma unroll
        for (int q = 0; q < 2; q++) {
            int f4 = tid + q * 128;
            int r = f4 >> 4, c4 = f4 & 15;
            size_t gi = (size_t)(b * NPATCH + tt + r) * 64 + c4 * 4;
            float4 v0 = *(const float4*)&dblp[gi];
            float4 v1 = *(const float4*)&dblp[gi + (size_t)MROWS * 64];
            float4 v2 = *(const float4*)&dblp[gi + (size_t)2 * MROWS * 64];
            float4 v3 = *(const float4*)&dblp[gi + (size_t)3 * MROWS * 64];
            *(float4*)&sdbl[r][c4 * 4] = make_float4(
                v0.x + v1.x + v2.x + v3.x, v0.y + v1.y + v2.y + v3.y,
                v0.z + v1.z + v2.z + v3.z, v0.w + v1.w + v2.w + v3.w);
        }
        __syncthreads();

        const int row0 = b * NPATCH + tt;
        float xi_c = xz[(size_t)row0 * 2 * DINNER + d];
        float zv_c = xz[(size_t)row0 * 2 * DINNER + DINNER + d];

        #pragma unroll 4
        for (int t2 = 0; t2 < 16; t2++) {
            float xi_n = 0.f, zv_n = 0.f;
            if (t2 < 15) {
                size_t r1 = (size_t)(row0 + t2 + 1);
                xi_n = xz[r1 * 2 * DINNER + d];
                zv_n = xz[r1 * 2 * DINNER + DINNER + d];
            }

            // inline causal conv + silu
            float ca = fmaf(xi_c, cw4.w,
                        fmaf(x1, cw4.z, fmaf(x2, cw4.y, fmaf(x3, cw4.x, cbv))));
            float xcv = ca / (1.f + __expf(-ca));
            x3 = x2; x2 = x1; x1 = xi_c;

            float dot = 0.f;
            #pragma unroll
            for (int j = 0; j < 8; j++)
                dot = fmaf(sdbl[t2][ng * 8 + j], swdt[dloc][ng * 8 + j], dot);
            dot += __shfl_xor_sync(0xffffffffu, dot, 1);
            dot += __shfl_xor_sync(0xffffffffu, dot, 2);
            float xv = dot + bv;

            float q, delta;
            if (xv > 0.f) {
                float e = __expf(-xv);
                q = e / (1.f + e);
                delta = xv + __logf(1.f + e);
            } else {
                float e = __expf(xv);
                q = 1.f / (1.f + e);
                delta = __logf(1.f + e);
            }

            float pw[4];
            if (structured) {
                float q2 = q * q, q4 = q2 * q2;
                float b1 = (ng & 1) ? q4 : 1.f;
                float b2 = (ng & 2) ? q4 * q4 : 1.f;
                float bs = b1 * b2;
                pw[0] = bs * q;      pw[1] = bs * q2;
                pw[2] = bs * q2 * q; pw[3] = bs * q4;
            } else {
                #pragma unroll
                for (int i = 0; i < 4; i++) pw[i] = __expf(delta * a[i]);
            }

            float dx = delta * xcv;
            float acc = 0.f;
            #pragma unroll
            for (int i = 0; i < 4; i++) {
                int n = ng * 4 + i;
                h[i] = fmaf(pw[i], h[i], dx * sdbl[t2][32 + n]);
                acc  = fmaf(h[i], sdbl[t2][48 + n], acc);
            }
            acc += __shfl_xor_sync(0xffffffffu, acc, 1);
            acc += __shfl_xor_sync(0xffffffffu, acc, 2);
            if (ng == 0) {
                float sz = zv_c / (1.f + __expf(-zv_c));
                float yv = (acc + xcv * Dv) * sz;
                __nv_bfloat16 hh, ll; split1(yv, hh, ll);
                size_t di = (size_t)(row0 + t2) * DINNER + d;
                g_yh[di] = hh; g_yl[di] = ll;
            }
            xi_c = xi_n; zv_c = zv_n;
        }
    }
}

// =====================================================================
// Head GEMM1: 256 split-K blocks, coalesced W staging
// =====================================================================
__global__ void __launch_bounds__(256)
k_head1(const float* __restrict__ hin, const float* __restrict__ W,
        float* __restrict__ part)
{
    const int z = blockIdx.x;
    const int kbase = z * (KFLAT / HKS);
    const int tid = threadIdx.x;
    const int j = tid & 127, g = tid >> 7;
    __shared__ float shw[128][65];
    __shared__ float shh[8][65];
    float acc[4] = {0.f, 0.f, 0.f, 0.f};

    for (int kc = 0; kc < KFLAT / HKS; kc += 64) {
        const int k0 = kbase + kc;
        #pragma unroll
        for (int i = tid; i < 128 * 16; i += 256) {
            int r = i >> 4, c4 = i & 15;
            float4 v = *(const float4*)&W[(size_t)r * KFLAT + k0 + c4 * 4];
            shw[r][c4*4+0] = v.x; shw[r][c4*4+1] = v.y;
            shw[r][c4*4+2] = v.z; shw[r][c4*4+3] = v.w;
        }
        if (tid < 128) {
            int r = tid >> 4, c4 = tid & 15;
            float4 v = *(const float4*)&hin[(size_t)r * KFLAT + k0 + c4 * 4];
            shh[r][c4*4+0] = v.x; shh[r][c4*4+1] = v.y;
            shh[r][c4*4+2] = v.z; shh[r][c4*4+3] = v.w;
        }
        __syncthreads();
        #pragma unroll 8
        for (int kk = 0; kk < 64; kk++) {
            float w = shw[j][kk];
            #pragma unroll
            for (int bq = 0; bq < 4; bq++)
                acc[bq] = fmaf(w, shh[g * 4 + bq][kk], acc[bq]);
        }
        __syncthreads();
    }
    #pragma unroll
    for (int bq = 0; bq < 4; bq++)
        part[(size_t)z * (BB * 128) + (g * 4 + bq) * 128 + j] = acc[bq];
}

__global__ void __launch_bounds__(128)
k_head2(const float* __restrict__ part, const float* __restrict__ hb1,
        const float* __restrict__ hW2,  const float* __restrict__ hb2,
        float* __restrict__ out)
{
    const int b = blockIdx.x;
    const int tid = threadIdx.x;
    __shared__ float g[128];
    float v = 0.f;
    for (int z = 0; z < HKS; z++)
        v += part[(size_t)z * (BB * 128) + b * 128 + tid];
    v += hb1[tid];
    g[tid] = 0.5f * v * (1.f + erff(v * 0.70710678118654752f));
    __syncthreads();
    if (tid < HPRED) {
        float acc = hb2[tid];
        #pragma unroll 16
        for (int j = 0; j < 128; j++)
            acc = fmaf(g[j], hW2[tid * 128 + j], acc);
        out[b * HPRED + tid] = acc;
    }
}

// =====================================================================
// Launch
// =====================================================================
static void* symaddr(const void* sym)
{
    void* p = nullptr;
    cudaGetSymbolAddress(&p, sym);
    return p;
}

#define STGBYTES(BM, BN) (2 * (BM) * 64 + 2 * (BN) * 64)
#define SMSZ(BM, BN) (3 * STGBYTES(BM, BN))

extern "C" void kernel_launch(void* const* d_in, const int* in_sizes, int n_in,
                              void* d_out, int out_size)
{
    const float* x      = (const float*)d_in[0];
    const float* in_g   = (const float*)d_in[1];
    const float* in_b   = (const float*)d_in[2];
    const float* pe_W   = (const float*)d_in[3];
    const float* pe_b   = (const float*)d_in[4];
    const float* ln_g   = (const float*)d_in[5];
    const float* ln_b   = (const float*)d_in[6];
    const float* W_in   = (const float*)d_in[7];
    const float* conv_W = (const float*)d_in[8];
    const float* conv_b = (const float*)d_in[9];
    const float* W_x    = (const float*)d_in[10];
    const float* W_dt   = (const float*)d_in[11];
    const float* b_dt   = (const float*)d_in[12];
    const float* A_log  = (const float*)d_in[13];
    const float* Dskip  = (const float*)d_in[14];
    const float* W_out  = (const float*)d_in[15];
    const float* fn_g   = (const float*)d_in[16];
    const float* fn_b   = (const float*)d_in[17];
    const float* hW1    = (const float*)d_in[18];
    const float* hb1    = (const float*)d_in[19];
    const float* hW2    = (const float*)d_in[20];
    const float* hb2    = (const float*)d_in[21];

    float* ph    = (float*)symaddr(g_h);
    float* pln   = (float*)symaddr(g_ln);
    float* pxz   = (float*)symaddr(g_xz);
    float* pdblp = (float*)symaddr(g_dblp);
    float* ppart = (float*)symaddr(g_part);

    __nv_bfloat16* pnh = (__nv_bfloat16*)symaddr(g_pnh);
    __nv_bfloat16* pnl = (__nv_bfloat16*)symaddr(g_pnl);
    __nv_bfloat16* lnh = (__nv_bfloat16*)symaddr(g_lnh);
    __nv_bfloat16* lnl = (__nv_bfloat16*)symaddr(g_lnl);
    __nv_bfloat16* yh  = (__nv_bfloat16*)symaddr(g_yh);
    __nv_bfloat16* yl  = (__nv_bfloat16*)symaddr(g_yl);

    __nv_bfloat16* peWh = (__nv_bfloat16*)symaddr(g_peWh);
    __nv_bfloat16* peWl = (__nv_bfloat16*)symaddr(g_peWl);
    __nv_bfloat16* Winh = (__nv_bfloat16*)symaddr(g_Winh);
    __nv_bfloat16* Winl = (__nv_bfloat16*)symaddr(g_Winl);
    __nv_bfloat16* Wxh  = (__nv_bfloat16*)symaddr(g_Wxh);
    __nv_bfloat16* Wxl  = (__nv_bfloat16*)symaddr(g_Wxl);
    __nv_bfloat16* Wouth= (__nv_bfloat16*)symaddr(g_Wouth);
    __nv_bfloat16* Woutl= (__nv_bfloat16*)symaddr(g_Woutl);

    static bool attr_done = false;
    if (!attr_done) {
        cudaFuncSetAttribute(bgemm<128,128,0>, cudaFuncAttributeMaxDynamicSharedMemorySize, SMSZ(128,128));
        cudaFuncSetAttribute(bgemm<64,128,1>,  cudaFuncAttributeMaxDynamicSharedMemorySize, SMSZ(64,128));
        cudaFuncSetAttribute(bgemm<64,128,2>,  cudaFuncAttributeMaxDynamicSharedMemorySize, SMSZ(64,128));
        cudaFuncSetAttribute(dgemm_conv,       cudaFuncAttributeMaxDynamicSharedMemorySize, SMSZ(64,64));
        attr_done = true;
    }

    // 0) fused prep: weight split + input LN/patch planes
    k_prep<<<1024, 256>>>(pe_W, W_in, W_x, W_out, x, in_g, in_b);

    // 1) patch embed (2048x512, K=128 padded)
    bgemm<64,128,1><<<dim3(DMOD/128, MROWS/64), 256, SMSZ(64,128)>>>(
        MROWS, DMOD, KPPAD, pnh, pnl, KPPAD, peWh, peWl, KPPAD, pe_b, ph, DMOD, 0);

    // 2) Mamba layers
    for (int i = 0; i < NLAY; i++) {
        k_lnw<1><<<MROWS/8, 256>>>(ph, nullptr, lnh, lnl,
                                   ln_g + i * DMOD, ln_b + i * DMOD);

        // xz = ln @ W_in^T  (2048 x 2048, K=512)
        bgemm<128,128,0><<<dim3(2*DINNER/128, MROWS/128), 256, SMSZ(128,128)>>>(
            MROWS, 2*DINNER, DMOD, lnh, lnl, DMOD,
            Winh + (size_t)i*2*DINNER*DMOD, Winl + (size_t)i*2*DINNER*DMOD, DMOD,
            nullptr, pxz, 2*DINNER, 0);

        // dbl partials = silu(conv(xi)) @ W_x^T, conv fused in loader
        dgemm_conv<<<dim3(1, MROWS/64, DBLKS), 256, SMSZ(64,64)>>>(
            pxz, conv_W + (size_t)i*DINNER*DCONV, conv_b + (size_t)i*DINNER,
            Wxh + (size_t)i*64*DINNER, Wxl + (size_t)i*64*DINNER, pdblp);

        // scan: inline conv window + delta GEMM + fused partial reduce
        k_scan<<<dim3(DINNER/32, BB), 128>>>(
            pxz, pdblp,
            W_dt + (size_t)i*DINNER*DTRANK, b_dt + (size_t)i*DINNER,
            conv_W + (size_t)i*DINNER*DCONV, conv_b + (size_t)i*DINNER,
            A_log + (size_t)i*DINNER*NST, Dskip + (size_t)i*DINNER);

        // h += y @ W_out^T  (2048 x 512, K=1024)
        bgemm<64,128,2><<<dim3(DMOD/128, MROWS/64), 256, SMSZ(64,128)>>>(
            MROWS, DMOD, DINNER, yh, yl, DINNER,
            Wouth + (size_t)i*DMOD*DINNER, Woutl + (size_t)i*DMOD*DINNER, DINNER,
            nullptr, ph, DMOD, 0);
    }

    // 3) final LN (fp32 for head)
    k_lnw<0><<<MROWS/8, 256>>>(ph, pln, nullptr, nullptr, fn_g, fn_b);

    // 4) head
    k_head1<<<HKS, 256>>>(pln, hW1, ppart);
    k_head2<<<BB, 128>>>(ppart, hb1, hW2, hb2, (float*)d_out);
}

// round 16
// speedup vs baseline: 1.0411x; 1.0411x over previous
#include <cuda_runtime.h>
#include <cuda_bf16.h>
#include <math.h>
#include <stdint.h>

// ---------------- Problem constants ----------------
#define BB      8
#define SEQLEN  4096
#define CINC    7
#define DMOD    512
#define NLAY    4
#define PLEN    16
#define NPATCH  256
#define NST     16
#define DCONV   4
#define DINNER  1024
#define DTRANK  32
#define MROWS   (BB*NPATCH)    // 2048
#define KPATCH  112
#define KPPAD   128
#define HPRED   96
#define HKS     256
#define KFLAT   (NPATCH*DMOD)  // 131072
#define DBLKS   4

// ---------------- fp32 scratch ----------------
__device__ float g_h   [MROWS*DMOD];
__device__ float g_ln  [MROWS*DMOD];
__device__ float g_xz  [MROWS*2*DINNER];
__device__ float g_dblp[DBLKS*MROWS*64];
__device__ float g_part[HKS*BB*128];

// ---------------- bf16 hi/lo activation planes ----------------
__device__ __nv_bfloat16 g_pnh[MROWS*KPPAD],  g_pnl[MROWS*KPPAD];
__device__ __nv_bfloat16 g_lnh[MROWS*DMOD],   g_lnl[MROWS*DMOD];
__device__ __nv_bfloat16 g_xch[MROWS*DINNER], g_xcl[MROWS*DINNER];
__device__ __nv_bfloat16 g_yh [MROWS*DINNER], g_yl [MROWS*DINNER];

// ---------------- bf16 hi/lo weight planes ----------------
__device__ __nv_bfloat16 g_peWh[DMOD*KPPAD],         g_peWl[DMOD*KPPAD];
__device__ __nv_bfloat16 g_Winh[NLAY*2*DINNER*DMOD], g_Winl[NLAY*2*DINNER*DMOD];
__device__ __nv_bfloat16 g_Wxh [NLAY*64*DINNER],     g_Wxl [NLAY*64*DINNER];
__device__ __nv_bfloat16 g_Wouth[NLAY*DMOD*DINNER],  g_Woutl[NLAY*DMOD*DINNER];

#define NWIN  (NLAY*2*DINNER*DMOD)
#define NWOUT (NLAY*DMOD*DINNER)
#define NWX   (NLAY*64*DINNER)

// =====================================================================
// Helpers
// =====================================================================
static __device__ __forceinline__ uint32_t smem_u32(const void* p) {
    uint32_t a;
    asm("{ .reg .u64 t; cvta.to.shared.u64 t, %1; cvt.u32.u64 %0, t; }"
        : "=r"(a) : "l"(p));
    return a;
}
static __device__ __forceinline__ void ldm_x4(uint32_t* r, uint32_t addr) {
    asm volatile("ldmatrix.sync.aligned.m8n8.x4.shared.b16 {%0,%1,%2,%3}, [%4];"
        : "=r"(r[0]), "=r"(r[1]), "=r"(r[2]), "=r"(r[3]) : "r"(addr));
}
static __device__ __forceinline__ void mma_bf16(float* c, const uint32_t* a,
                                                const uint32_t* b) {
    asm volatile(
        "mma.sync.aligned.m16n8k16.row.col.f32.bf16.bf16.f32 "
        "{%0,%1,%2,%3}, {%4,%5,%6,%7}, {%8,%9}, {%0,%1,%2,%3};"
        : "+f"(c[0]), "+f"(c[1]), "+f"(c[2]), "+f"(c[3])
        : "r"(a[0]), "r"(a[1]), "r"(a[2]), "r"(a[3]), "r"(b[0]), "r"(b[1]));
}
static __device__ __forceinline__ void cp16(uint32_t dst, const void* src) {
    asm volatile("cp.async.cg.shared.global [%0], [%1], 16;"
                 :: "r"(dst), "l"(src));
}
static __device__ __forceinline__ void cp_commit() {
    asm volatile("cp.async.commit_group;");
}
template<int NW> static __device__ __forceinline__ void cp_wait() {
    asm volatile("cp.async.wait_group %0;" :: "n"(NW));
}
static __device__ __forceinline__ void split1(float v, __nv_bfloat16& h, __nv_bfloat16& l) {
    h = __float2bfloat16(v);
    l = __float2bfloat16(v - __bfloat162float(h));
}
static __device__ __forceinline__ uint32_t pk2(__nv_bfloat16 a, __nv_bfloat16 b) {
    return (uint32_t)__bfloat16_as_ushort(a) | ((uint32_t)__bfloat16_as_ushort(b) << 16);
}
static __device__ __forceinline__ void split4v(float4 v, uint2& h, uint2& l) {
    __nv_bfloat16 h0,l0,h1,l1,h2,l2,h3,l3;
    split1(v.x,h0,l0); split1(v.y,h1,l1); split1(v.z,h2,l2); split1(v.w,h3,l3);
    h = make_uint2(pk2(h0,h1), pk2(h2,h3));
    l = make_uint2(pk2(l0,l1), pk2(l2,l3));
}
static __device__ __forceinline__ uint32_t swz64(int row, int u) {
    return (uint32_t)(row * 64 + ((u ^ ((row >> 1) & 3)) << 4));
}

// =====================================================================
// Fused prep: weight split + input patchnorm in ONE launch
// =====================================================================
__global__ void __launch_bounds__(256)
k_prep(const float* __restrict__ peW, const float* __restrict__ Win,
       const float* __restrict__ Wx,  const float* __restrict__ Wout,
       const float* __restrict__ x,   const float* __restrict__ in_g,
       const float* __restrict__ in_b)
{
    const int t0 = blockIdx.x * blockDim.x + threadIdx.x;
    const int stride = gridDim.x * blockDim.x;
    constexpr int T1 = NWIN / 4;
    constexpr int T2 = T1 + NWOUT / 4;
    constexpr int T3 = T2 + NWX / 4;

    for (int i4 = t0; i4 < T3; i4 += stride) {
        const float* src; __nv_bfloat16 *dh, *dl; int off;
        if (i4 < T1)      { src = Win;  dh = g_Winh;  dl = g_Winl;  off = i4; }
        else if (i4 < T2) { src = Wout; dh = g_Wouth; dl = g_Woutl; off = i4 - T1; }
        else              { src = Wx;   dh = g_Wxh;   dl = g_Wxl;   off = i4 - T2; }
        float4 v = *(const float4*)&src[(size_t)off * 4];
        uint2 h, l; split4v(v, h, l);
        *(uint2*)&dh[(size_t)off * 4] = h;
        *(uint2*)&dl[(size_t)off * 4] = l;
    }
    for (int i4 = t0; i4 < DMOD * (KPATCH / 4); i4 += stride) {
        int r = i4 / (KPATCH / 4), c4 = i4 % (KPATCH / 4);
        float4 v = *(const float4*)&peW[(size_t)r * KPATCH + c4 * 4];
        uint2 h, l; split4v(v, h, l);
        *(uint2*)&g_peWh[(size_t)r * KPPAD + c4 * 4] = h;
        *(uint2*)&g_peWl[(size_t)r * KPPAD + c4 * 4] = l;
    }
    for (int idx = t0; idx < BB * SEQLEN; idx += stride) {
        int b = idx / SEQLEN, s = idx % SEQLEN;
        const float* xp = x + idx * CINC;
        float sum = 0.f;
        #pragma unroll
        for (int c = 0; c < CINC; c++) sum += xp[c];
        float m = sum * (1.f / CINC);
        float var = 0.f;
        #pragma unroll
        for (int c = 0; c < CINC; c++) { float d = xp[c] - m; var = fmaf(d, d, var); }
        var *= (1.f / CINC);
        float inv = rsqrtf(var + 1e-5f);
        int n = s / PLEN, p = s % PLEN;
        size_t ro = (size_t)(b * NPATCH + n) * KPPAD;
        #pragma unroll
        for (int c = 0; c < CINC; c++) {
            float v = (xp[c] - m) * inv * in_g[c] + in_b[c];
            __nv_bfloat16 h, l; split1(v, h, l);
            g_pnh[ro + c * PLEN + p] = h;
            g_pnl[ro + c * PLEN + p] = l;
        }
    }
}

// =====================================================================
// bf16x3 mma.sync GEMM: swizzled SMEM, 3-stage cp.async.
// EPI: 0=store, 1=store+bias[n], 2=accumulate into C
// =====================================================================
template<int BM, int BN, int EPI>
__global__ void __launch_bounds__(256, 2)
bgemm(int M, int N, int Ks,
      const __nv_bfloat16* __restrict__ Ah, const __nv_bfloat16* __restrict__ Al, int lda,
      const __nv_bfloat16* __restrict__ Wh, const __nv_bfloat16* __restrict__ Wl, int ldw,
      const float* __restrict__ bias, float* __restrict__ C, int ldc, int sliceC)
{
    constexpr int WNW = (BM == 128) ? 2 : 4;
    constexpr int WN  = BN / WNW;
    constexpr int NT8 = WN / 8;
    constexpr int APLB = BM * 64;
    constexpr int WPLB = BN * 64;
    constexpr int STGB = 2 * APLB + 2 * WPLB;

    extern __shared__ __nv_bfloat16 sm[];
    const uint32_t smu = smem_u32(sm);

    const int tid = threadIdx.x, lane = tid & 31, warp = tid >> 5;
    const int wn = warp % WNW, wm = warp / WNW;
    const int mB = blockIdx.y * BM, nB = blockIdx.x * BN;
    const int kbase = blockIdx.z * Ks;
    float* pC = C + (size_t)blockIdx.z * sliceC;

    float acc[2][NT8][4];
    #pragma unroll
    for (int t = 0; t < 2; t++)
        #pragma unroll
        for (int j = 0; j < NT8; j++)
            #pragma unroll
            for (int r = 0; r < 4; r++) acc[t][j][r] = 0.f;

    const int nCh = Ks / 32;

    auto load_stage = [&](int s) {
        const uint32_t sb = smu + (uint32_t)((s % 3) * STGB);
        const int k0 = kbase + s * 32;
        #pragma unroll
        for (int i = tid; i < BM * 4; i += 256) {
            int row = i >> 2, u = i & 3;
            size_t g = (size_t)(mB + row) * lda + k0 + u * 8;
            uint32_t d = sb + swz64(row, u);
            cp16(d, Ah + g);
            cp16(d + APLB, Al + g);
        }
        #pragma unroll
        for (int i = tid; i < BN * 4; i += 256) {
            int row = i >> 2, u = i & 3;
            size_t g = (size_t)(nB + row) * ldw + k0 + u * 8;
            uint32_t d = sb + 2 * APLB + swz64(row, u);
            cp16(d, Wh + g);
            cp16(d + WPLB, Wl + g);
        }
        cp_commit();
    };

    load_stage(0);
    if (nCh > 1) load_stage(1); else cp_commit();

    for (int s = 0; s < nCh; s++) {
        if (s + 2 < nCh) load_stage(s + 2); else cp_commit();
        cp_wait<2>();
        __syncthreads();

        const uint32_t sb = smu + (uint32_t)((s % 3) * STGB);
        #pragma unroll
        for (int k16 = 0; k16 < 2; k16++) {
            uint32_t ah[2][4], al[2][4], wf[NT8][2];
            const int arow = wm * 32 + (lane & 15);
            const int au   = k16 * 2 + (lane >> 4);
            const uint32_t aAddr = sb + swz64(arow, au);
            ldm_x4(ah[0], aAddr);
            ldm_x4(ah[1], aAddr + 16 * 64);

            const int wrow = wn * WN + ((lane >> 4) << 3) + (lane & 7);
            const int wu   = k16 * 2 + ((lane >> 3) & 1);
            const uint32_t wAddr = sb + 2 * APLB + swz64(wrow, wu);
            #pragma unroll
            for (int jp = 0; jp < NT8 / 2; jp++) {
                uint32_t t4[4];
                ldm_x4(t4, wAddr + jp * 16 * 64);
                wf[2*jp][0] = t4[0]; wf[2*jp][1] = t4[1];
                wf[2*jp+1][0] = t4[2]; wf[2*jp+1][1] = t4[3];
            }
            #pragma unroll
            for (int t = 0; t < 2; t++)
                #pragma unroll
                for (int j = 0; j < NT8; j++) mma_bf16(acc[t][j], ah[t], wf[j]);

            ldm_x4(al[0], aAddr + APLB);
            ldm_x4(al[1], aAddr + APLB + 16 * 64);
            #pragma unroll
            for (int t = 0; t < 2; t++)
                #pragma unroll
                for (int j = 0; j < NT8; j++) mma_bf16(acc[t][j], al[t], wf[j]);

            #pragma unroll
            for (int jp = 0; jp < NT8 / 2; jp++) {
                uint32_t t4[4];
                ldm_x4(t4, wAddr + WPLB + jp * 16 * 64);
                wf[2*jp][0] = t4[0]; wf[2*jp][1] = t4[1];
                wf[2*jp+1][0] = t4[2]; wf[2*jp+1][1] = t4[3];
            }
            #pragma unroll
            for (int t = 0; t < 2; t++)
                #pragma unroll
                for (int j = 0; j < NT8; j++) mma_bf16(acc[t][j], ah[t], wf[j]);
        }
        __syncthreads();
    }

    #pragma unroll
    for (int t = 0; t < 2; t++) {
        const int m = mB + wm * 32 + t * 16 + (lane >> 2);
        #pragma unroll
        for (int j = 0; j < NT8; j++) {
            const int n = nB + wn * WN + j * 8 + (lane & 3) * 2;
            float2 v0 = make_float2(acc[t][j][0], acc[t][j][1]);
            float2 v1 = make_float2(acc[t][j][2], acc[t][j][3]);
            if (EPI == 1) {
                float b0 = bias[n], b1 = bias[n + 1];
                v0.x += b0; v0.y += b1; v1.x += b0; v1.y += b1;
            }
            if (EPI == 2) {
                float2 p0 = *(const float2*)&pC[(size_t)m * ldc + n];
                float2 p1 = *(const float2*)&pC[(size_t)(m + 8) * ldc + n];
                v0.x += p0.x; v0.y += p0.y; v1.x += p1.x; v1.y += p1.y;
            }
            *(float2*)&pC[(size_t)m * ldc + n]       = v0;
            *(float2*)&pC[(size_t)(m + 8) * ldc + n] = v1;
        }
    }
}

// =====================================================================
// Warp-per-row layernorm (width 512). SPLIT=1: bf16 planes; 0: fp32.
// =====================================================================
template<int SPLIT>
__global__ void __launch_bounds__(256)
k_lnw(const float* __restrict__ in, float* __restrict__ outf,
      __nv_bfloat16* __restrict__ oh, __nv_bfloat16* __restrict__ ol,
      const float* __restrict__ gam, const float* __restrict__ bet)
{
    const int row  = blockIdx.x * 8 + (threadIdx.x >> 5);
    const int lane = threadIdx.x & 31;
    const float* x = in + (size_t)row * DMOD;

    float4 v[4];
    float s = 0.f, ss = 0.f;
    #pragma unroll
    for (int i = 0; i < 4; i++) {
        v[i] = *(const float4*)&x[i * 128 + lane * 4];
        s  += v[i].x + v[i].y + v[i].z + v[i].w;
        ss += v[i].x*v[i].x + v[i].y*v[i].y + v[i].z*v[i].z + v[i].w*v[i].w;
    }
    #pragma unroll
    for (int o = 16; o > 0; o >>= 1) {
        s  += __shfl_xor_sync(0xffffffffu, s,  o);
        ss += __shfl_xor_sync(0xffffffffu, ss, o);
    }
    float m   = s * (1.f / DMOD);
    float var = ss * (1.f / DMOD) - m * m;
    float inv = rsqrtf(var + 1e-5f);

    #pragma unroll
    for (int i = 0; i < 4; i++) {
        int c = i * 128 + lane * 4;
        float4 g = *(const float4*)&gam[c];
        float4 bb = *(const float4*)&bet[c];
        float o0 = (v[i].x - m) * inv * g.x + bb.x;
        float o1 = (v[i].y - m) * inv * g.y + bb.y;
        float o2 = (v[i].z - m) * inv * g.z + bb.z;
        float o3 = (v[i].w - m) * inv * g.w + bb.w;
        if (SPLIT) {
            float4 vv = make_float4(o0, o1, o2, o3);
            uint2 h, l; split4v(vv, h, l);
            size_t off = (size_t)row * DMOD + c;
            *(uint2*)&oh[off] = h;
            *(uint2*)&ol[off] = l;
        } else {
            *(float4*)&outf[(size_t)row * DMOD + c] = make_float4(o0, o1, o2, o3);
        }
    }
}

// =====================================================================
// Depthwise causal conv (DC=4) + silu, 2 channels/thread
// =====================================================================
__global__ void __launch_bounds__(256)
k_conv(const float* __restrict__ xz,
       const float* __restrict__ cw,
       const float* __restrict__ cb)
{
    int idx = blockIdx.x * blockDim.x + threadIdx.x;
    if (idx >= MROWS * DINNER / 2) return;
    int d2 = idx % (DINNER / 2);
    int bl = idx / (DINNER / 2);
    int d  = d2 * 2;
    int l  = bl % NPATCH;
    int b  = bl / NPATCH;
    const float4 w0 = *(const float4*)(cw + d * 4);
    const float4 w1 = *(const float4*)(cw + d * 4 + 4);
    float2 cbv = *(const float2*)(cb + d);
    float a0 = cbv.x, a1 = cbv.y;
    size_t base = (size_t)(b * NPATCH) * 2 * DINNER + d;
    float2 t;
    if (l >= 3) { t = *(const float2*)&xz[base + (size_t)(l-3)*2*DINNER];
                  a0 = fmaf(t.x, w0.x, a0); a1 = fmaf(t.y, w1.x, a1); }
    if (l >= 2) { t = *(const float2*)&xz[base + (size_t)(l-2)*2*DINNER];
                  a0 = fmaf(t.x, w0.y, a0); a1 = fmaf(t.y, w1.y, a1); }
    if (l >= 1) { t = *(const float2*)&xz[base + (size_t)(l-1)*2*DINNER];
                  a0 = fmaf(t.x, w0.z, a0); a1 = fmaf(t.y, w1.z, a1); }
    t = *(const float2*)&xz[base + (size_t)l*2*DINNER];
    a0 = fmaf(t.x, w0.w, a0); a1 = fmaf(t.y, w1.w, a1);
    float v0 = a0 / (1.f + __expf(-a0));
    float v1 = a1 / (1.f + __expf(-a1));
    __nv_bfloat16 h0, l0, h1, l1;
    split1(v0, h0, l0); split1(v1, h1, l1);
    size_t o = (size_t)bl * DINNER + d;
    *(uint32_t*)&g_xch[o] = pk2(h0, h1);
    *(uint32_t*)&g_xcl[o] = pk2(l0, l1);
}

// =====================================================================
// Selective scan v2: per-tile PARALLEL precompute of (q, delta), then a
// short-critical-path serial recurrence. Fused dbl split-K reduce.
// 4 lanes per (b,d). Writes y hi/lo planes.
// =====================================================================
__global__ void __launch_bounds__(128)
k_scan(const float* __restrict__ xz,  const float* __restrict__ dblp,
       const float* __restrict__ Wdt, const float* __restrict__ bdt,
       const float* __restrict__ A_log, const float* __restrict__ Dskip)
{
    const int tid  = threadIdx.x;
    const int ng   = tid & 3;
    const int dloc = tid >> 2;
    const int d    = blockIdx.x * 32 + dloc;
    const int b    = blockIdx.y;

    __shared__ float sdbl[16][68];     // dt|B|C, padded for bank-safe col reads
    __shared__ float swdt[32][33];
    __shared__ float sq [16][32];      // precomputed q   = sigmoid(-xv)
    __shared__ float sdl[16][32];      // precomputed delta = softplus(xv)

    {
        int r = tid >> 2, c0 = (tid & 3) * 8;
        #pragma unroll
        for (int j = 0; j < 8; j++)
            swdt[r][c0 + j] = Wdt[(blockIdx.x * 32 + r) * DTRANK + c0 + j];
    }
    const float bv = bdt[d];

    float a[4];
    bool structured = true;
    #pragma unroll
    for (int i = 0; i < 4; i++) {
        int n = ng * 4 + i;
        a[i] = -__expf(A_log[d * NST + n]);
        structured = structured && (fabsf(a[i] + (float)(n + 1)) <= 1e-4f * (float)(n + 1));
    }
    const float Dv = Dskip[d];
    float h[4] = {0.f, 0.f, 0.f, 0.f};

    for (int tt = 0; tt < NPATCH; tt += 16) {
        __syncthreads();
        // stage dt|B|C with fused 4-way split-K reduce
        #pragma unroll
        for (int q8 = 0; q8 < 2; q8++) {
            int f4 = tid + q8 * 128;
            int r = f4 >> 4, c4 = f4 & 15;
            size_t gi = (size_t)(b * NPATCH + tt + r) * 64 + c4 * 4;
            float4 v0 = *(const float4*)&dblp[gi];
            float4 v1 = *(const float4*)&dblp[gi + (size_t)MROWS * 64];
            float4 v2 = *(const float4*)&dblp[gi + (size_t)2 * MROWS * 64];
            float4 v3 = *(const float4*)&dblp[gi + (size_t)3 * MROWS * 64];
            *(float4*)&sdbl[r][c4 * 4] = make_float4(
                v0.x + v1.x + v2.x + v3.x, v0.y + v1.y + v2.y + v3.y,
                v0.z + v1.z + v2.z + v3.z, v0.w + v1.w + v2.w + v3.w);
        }
        __syncthreads();

        // PARALLEL phase: each thread computes xv -> (q, delta) for 4 t2's
        #pragma unroll
        for (int tt2 = 0; tt2 < 4; tt2++) {
            int t2 = tt2 * 4 + ng;
            float d0 = bv, d1 = 0.f;
            #pragma unroll
            for (int j = 0; j < 16; j++) {
                d0 = fmaf(sdbl[t2][2*j],     swdt[dloc][2*j],     d0);
                d1 = fmaf(sdbl[t2][2*j + 1], swdt[dloc][2*j + 1], d1);
            }
            float xv = d0 + d1;
            float q, delta;
            if (xv > 0.f) {
                float e = __expf(-xv);
                q = e / (1.f + e);
                delta = xv + __logf(1.f + e);
            } else {
                float e = __expf(xv);
                q = 1.f / (1.f + e);
                delta = __logf(1.f + e);
            }
            sq [t2][dloc] = q;
            sdl[t2][dloc] = delta;
        }
        __syncthreads();

        // SERIAL recurrence: critical path is one FMA per state per step
        const int row0 = b * NPATCH + tt;
        float xch_c = __bfloat162float(g_xch[(size_t)row0 * DINNER + d]);
        float xcl_c = __bfloat162float(g_xcl[(size_t)row0 * DINNER + d]);
        float zv_c  = xz[(size_t)row0 * 2 * DINNER + DINNER + d];

        #pragma unroll 4
        for (int t2 = 0; t2 < 16; t2++) {
            float xch_n = 0.f, xcl_n = 0.f, zv_n = 0.f;
            if (t2 < 15) {
                size_t r1 = (size_t)(row0 + t2 + 1);
                xch_n = __bfloat162float(g_xch[r1 * DINNER + d]);
                xcl_n = __bfloat162float(g_xcl[r1 * DINNER + d]);
                zv_n  = xz[r1 * 2 * DINNER + DINNER + d];
            }
            float q     = sq [t2][dloc];
            float delta = sdl[t2][dloc];

            float pw[4];
            if (structured) {
                float q2 = q * q, q4 = q2 * q2;
                float b1 = (ng & 1) ? q4 : 1.f;
                float b2 = (ng & 2) ? q4 * q4 : 1.f;
                float bs = b1 * b2;
                pw[0] = bs * q;      pw[1] = bs * q2;
                pw[2] = bs * q2 * q; pw[3] = bs * q4;
            } else {
                #pragma unroll
                for (int i = 0; i < 4; i++) pw[i] = __expf(delta * a[i]);
            }

            float xcv = xch_c + xcl_c;
            float dx = delta * xcv;
            float acc = 0.f;
            #pragma unroll
            for (int i = 0; i < 4; i++) {
                int n = ng * 4 + i;
                h[i] = fmaf(pw[i], h[i], dx * sdbl[t2][32 + n]);
                acc  = fmaf(h[i], sdbl[t2][48 + n], acc);
            }
            acc += __shfl_xor_sync(0xffffffffu, acc, 1);
            acc += __shfl_xor_sync(0xffffffffu, acc, 2);
            if (ng == 0) {
                float sz = zv_c / (1.f + __expf(-zv_c));
                float yv = (acc + xcv * Dv) * sz;
                __nv_bfloat16 hh, ll; split1(yv, hh, ll);
                size_t di = (size_t)(row0 + t2) * DINNER + d;
                g_yh[di] = hh; g_yl[di] = ll;
            }
            xch_c = xch_n; xcl_c = xcl_n; zv_c = zv_n;
        }
    }
}

// =====================================================================
// Head GEMM1: 256 split-K blocks, coalesced W staging
// =====================================================================
__global__ void __launch_bounds__(256)
k_head1(const float* __restrict__ hin, const float* __restrict__ W,
        float* __restrict__ part)
{
    const int z = blockIdx.x;
    const int kbase = z * (KFLAT / HKS);
    const int tid = threadIdx.x;
    const int j = tid & 127, g = tid >> 7;
    __shared__ float shw[128][65];
    __shared__ float shh[8][65];
    float acc[4] = {0.f, 0.f, 0.f, 0.f};

    for (int kc = 0; kc < KFLAT / HKS; kc += 64) {
        const int k0 = kbase + kc;
        #pragma unroll
        for (int i = tid; i < 128 * 16; i += 256) {
            int r = i >> 4, c4 = i & 15;
            float4 v = *(const float4*)&W[(size_t)r * KFLAT + k0 + c4 * 4];
            shw[r][c4*4+0] = v.x; shw[r][c4*4+1] = v.y;
            shw[r][c4*4+2] = v.z; shw[r][c4*4+3] = v.w;
        }
        if (tid < 128) {
            int r = tid >> 4, c4 = tid & 15;
            float4 v = *(const float4*)&hin[(size_t)r * KFLAT + k0 + c4 * 4];
            shh[r][c4*4+0] = v.x; shh[r][c4*4+1] = v.y;
            shh[r][c4*4+2] = v.z; shh[r][c4*4+3] = v.w;
        }
        __syncthreads();
        #pragma unroll 8
        for (int kk = 0; kk < 64; kk++) {
            float w = shw[j][kk];
            #pragma unroll
            for (int bq = 0; bq < 4; bq++)
                acc[bq] = fmaf(w, shh[g * 4 + bq][kk], acc[bq]);
        }
        __syncthreads();
    }
    #pragma unroll
    for (int bq = 0; bq < 4; bq++)
        part[(size_t)z * (BB * 128) + (g * 4 + bq) * 128 + j] = acc[bq];
}

__global__ void __launch_bounds__(128)
k_head2(const float* __restrict__ part, const float* __restrict__ hb1,
        const float* __restrict__ hW2,  const float* __restrict__ hb2,
        float* __restrict__ out)
{
    const int b = blockIdx.x;
    const int tid = threadIdx.x;
    __shared__ float g[128];
    float v = 0.f;
    for (int z = 0; z < HKS; z++)
        v += part[(size_t)z * (BB * 128) + b * 128 + tid];
    v += hb1[tid];
    g[tid] = 0.5f * v * (1.f + erff(v * 0.70710678118654752f));
    __syncthreads();
    if (tid < HPRED) {
        float acc = hb2[tid];
        #pragma unroll 16
        for (int j = 0; j < 128; j++)
            acc = fmaf(g[j], hW2[tid * 128 + j], acc);
        out[b * HPRED + tid] = acc;
    }
}

// =====================================================================
// Launch
// =====================================================================
static void* symaddr(const void* sym)
{
    void* p = nullptr;
    cudaGetSymbolAddress(&p, sym);
    return p;
}

#define STGBYTES(BM, BN) (2 * (BM) * 64 + 2 * (BN) * 64)
#define SMSZ(BM, BN) (3 * STGBYTES(BM, BN))

extern "C" void kernel_launch(void* const* d_in, const int* in_sizes, int n_in,
                              void* d_out, int out_size)
{
    const float* x      = (const float*)d_in[0];
    const float* in_g   = (const float*)d_in[1];
    const float* in_b   = (const float*)d_in[2];
    const float* pe_W   = (const float*)d_in[3];
    const float* pe_b   = (const float*)d_in[4];
    const float* ln_g   = (const float*)d_in[5];
    const float* ln_b   = (const float*)d_in[6];
    const float* W_in   = (const float*)d_in[7];
    const float* conv_W = (const float*)d_in[8];
    const float* conv_b = (const float*)d_in[9];
    const float* W_x    = (const float*)d_in[10];
    const float* W_dt   = (const float*)d_in[11];
    const float* b_dt   = (const float*)d_in[12];
    const float* A_log  = (const float*)d_in[13];
    const float* Dskip  = (const float*)d_in[14];
    const float* W_out  = (const float*)d_in[15];
    const float* fn_g   = (const float*)d_in[16];
    const float* fn_b   = (const float*)d_in[17];
    const float* hW1    = (const float*)d_in[18];
    const float* hb1    = (const float*)d_in[19];
    const float* hW2    = (const float*)d_in[20];
    const float* hb2    = (const float*)d_in[21];

    float* ph    = (float*)symaddr(g_h);
    float* pln   = (float*)symaddr(g_ln);
    float* pxz   = (float*)symaddr(g_xz);
    float* pdblp = (float*)symaddr(g_dblp);
    float* ppart = (float*)symaddr(g_part);

    __nv_bfloat16* pnh = (__nv_bfloat16*)symaddr(g_pnh);
    __nv_bfloat16* pnl = (__nv_bfloat16*)symaddr(g_pnl);
    __nv_bfloat16* lnh = (__nv_bfloat16*)symaddr(g_lnh);
    __nv_bfloat16* lnl = (__nv_bfloat16*)symaddr(g_lnl);
    __nv_bfloat16* xch = (__nv_bfloat16*)symaddr(g_xch);
    __nv_bfloat16* xcl = (__nv_bfloat16*)symaddr(g_xcl);
    __nv_bfloat16* yh  = (__nv_bfloat16*)symaddr(g_yh);
    __nv_bfloat16* yl  = (__nv_bfloat16*)symaddr(g_yl);

    __nv_bfloat16* peWh = (__nv_bfloat16*)symaddr(g_peWh);
    __nv_bfloat16* peWl = (__nv_bfloat16*)symaddr(g_peWl);
    __nv_bfloat16* Winh = (__nv_bfloat16*)symaddr(g_Winh);
    __nv_bfloat16* Winl = (__nv_bfloat16*)symaddr(g_Winl);
    __nv_bfloat16* Wxh  = (__nv_bfloat16*)symaddr(g_Wxh);
    __nv_bfloat16* Wxl  = (__nv_bfloat16*)symaddr(g_Wxl);
    __nv_bfloat16* Wouth= (__nv_bfloat16*)symaddr(g_Wouth);
    __nv_bfloat16* Woutl= (__nv_bfloat16*)symaddr(g_Woutl);

    static bool attr_done = false;
    if (!attr_done) {
        cudaFuncSetAttribute(bgemm<128,128,0>, cudaFuncAttributeMaxDynamicSharedMemorySize, SMSZ(128,128));
        cudaFuncSetAttribute(bgemm<64,128,1>,  cudaFuncAttributeMaxDynamicSharedMemorySize, SMSZ(64,128));
        cudaFuncSetAttribute(bgemm<64,128,2>,  cudaFuncAttributeMaxDynamicSharedMemorySize, SMSZ(64,128));
        cudaFuncSetAttribute(bgemm<64,64,0>,   cudaFuncAttributeMaxDynamicSharedMemorySize, SMSZ(64,64));
        attr_done = true;
    }

    // 0) fused prep: weight split + input LN/patch planes
    k_prep<<<1024, 256>>>(pe_W, W_in, W_x, W_out, x, in_g, in_b);

    // 1) patch embed (2048x512, K=128 padded)
    bgemm<64,128,1><<<dim3(DMOD/128, MROWS/64), 256, SMSZ(64,128)>>>(
        MROWS, DMOD, KPPAD, pnh, pnl, KPPAD, peWh, peWl, KPPAD, pe_b, ph, DMOD, 0);

    // 2) Mamba layers
    for (int i = 0; i < NLAY; i++) {
        k_lnw<1><<<MROWS/8, 256>>>(ph, nullptr, lnh, lnl,
                                   ln_g + i * DMOD, ln_b + i * DMOD);

        // xz = ln @ W_in^T  (2048 x 2048, K=512)
        bgemm<128,128,0><<<dim3(2*DINNER/128, MROWS/128), 256, SMSZ(128,128)>>>(
            MROWS, 2*DINNER, DMOD, lnh, lnl, DMOD,
            Winh + (size_t)i*2*DINNER*DMOD, Winl + (size_t)i*2*DINNER*DMOD, DMOD,
            nullptr, pxz, 2*DINNER, 0);

        k_conv<<<(MROWS * DINNER / 2 + 255) / 256, 256>>>(
            pxz, conv_W + (size_t)i*DINNER*DCONV, conv_b + (size_t)i*DINNER);

        // dbl partial = xc @ W_x^T  (2048 x 64, K split 4 x 256)
        bgemm<64,64,0><<<dim3(1, MROWS/64, DBLKS), 256, SMSZ(64,64)>>>(
            MROWS, 64, DINNER/DBLKS, xch, xcl, DINNER,
            Wxh + (size_t)i*64*DINNER, Wxl + (size_t)i*64*DINNER, DINNER,
            nullptr, pdblp, 64, MROWS*64);

        // scan v2 (parallel q/delta precompute + fused partial reduce)
        k_scan<<<dim3(DINNER/32, BB), 128>>>(
            pxz, pdblp,
            W_dt + (size_t)i*DINNER*DTRANK, b_dt + (size_t)i*DINNER,
            A_log + (size_t)i*DINNER*NST, Dskip + (size_t)i*DINNER);

        // h += y @ W_out^T  (2048 x 512, K=1024)
        bgemm<64,128,2><<<dim3(DMOD/128, MROWS/64), 256, SMSZ(64,128)>>>(
            MROWS, DMOD, DINNER, yh, yl, DINNER,
            Wouth + (size_t)i*DMOD*DINNER, Woutl + (size_t)i*DMOD*DINNER, DINNER,
            nullptr, ph, DMOD, 0);
    }

    // 3) final LN (fp32 for head)
    k_lnw<0><<<MROWS/8, 256>>>(ph, pln, nullptr, nullptr, fn_g, fn_b);

    // 4) head
    k_head1<<<HKS, 256>>>(pln, hW1, ppart);
    k_head2<<<BB, 128>>>(ppart, hb1, hW2, hb2, (float*)d_out);
}

// round 17
// speedup vs baseline: 1.0736x; 1.0312x over previous
#include <cuda_runtime.h>
#include <cuda_bf16.h>
#include <math.h>
#include <stdint.h>

// ---------------- Problem constants ----------------
#define BB      8
#define SEQLEN  4096
#define CINC    7
#define DMOD    512
#define NLAY    4
#define PLEN    16
#define NPATCH  256
#define NST     16
#define DCONV   4
#define DINNER  1024
#define DTRANK  32
#define MROWS   (BB*NPATCH)    // 2048
#define KPATCH  112
#define KPPAD   128
#define HPRED   96
#define HKS     256
#define KFLAT   (NPATCH*DMOD)  // 131072
#define DBLKS   4
#define WOKS    2              // W_out split-K

// ---------------- fp32 scratch ----------------
__device__ float g_h   [MROWS*DMOD];
__device__ float g_ln  [MROWS*DMOD];
__device__ float g_xz  [MROWS*2*DINNER];
__device__ float g_dblp[DBLKS*MROWS*64];
__device__ float g_wop [WOKS*MROWS*DMOD];
__device__ float g_part[HKS*BB*128];

// ---------------- bf16 hi/lo activation planes ----------------
__device__ __nv_bfloat16 g_pnh[MROWS*KPPAD],  g_pnl[MROWS*KPPAD];
__device__ __nv_bfloat16 g_lnh[MROWS*DMOD],   g_lnl[MROWS*DMOD];
__device__ __nv_bfloat16 g_xch[MROWS*DINNER], g_xcl[MROWS*DINNER];
__device__ __nv_bfloat16 g_yh [MROWS*DINNER], g_yl [MROWS*DINNER];

// ---------------- bf16 hi/lo weight planes ----------------
__device__ __nv_bfloat16 g_peWh[DMOD*KPPAD],         g_peWl[DMOD*KPPAD];
__device__ __nv_bfloat16 g_Winh[NLAY*2*DINNER*DMOD], g_Winl[NLAY*2*DINNER*DMOD];
__device__ __nv_bfloat16 g_Wxh [NLAY*64*DINNER],     g_Wxl [NLAY*64*DINNER];
__device__ __nv_bfloat16 g_Wouth[NLAY*DMOD*DINNER],  g_Woutl[NLAY*DMOD*DINNER];

#define NWIN  (NLAY*2*DINNER*DMOD)
#define NWOUT (NLAY*DMOD*DINNER)
#define NWX   (NLAY*64*DINNER)

// =====================================================================
// Helpers
// =====================================================================
static __device__ __forceinline__ uint32_t smem_u32(const void* p) {
    uint32_t a;
    asm("{ .reg .u64 t; cvta.to.shared.u64 t, %1; cvt.u32.u64 %0, t; }"
        : "=r"(a) : "l"(p));
    return a;
}
static __device__ __forceinline__ void ldm_x4(uint32_t* r, uint32_t addr) {
    asm volatile("ldmatrix.sync.aligned.m8n8.x4.shared.b16 {%0,%1,%2,%3}, [%4];"
        : "=r"(r[0]), "=r"(r[1]), "=r"(r[2]), "=r"(r[3]) : "r"(addr));
}
static __device__ __forceinline__ void mma_bf16(float* c, const uint32_t* a,
                                                const uint32_t* b) {
    asm volatile(
        "mma.sync.aligned.m16n8k16.row.col.f32.bf16.bf16.f32 "
        "{%0,%1,%2,%3}, {%4,%5,%6,%7}, {%8,%9}, {%0,%1,%2,%3};"
        : "+f"(c[0]), "+f"(c[1]), "+f"(c[2]), "+f"(c[3])
        : "r"(a[0]), "r"(a[1]), "r"(a[2]), "r"(a[3]), "r"(b[0]), "r"(b[1]));
}
static __device__ __forceinline__ void cp16(uint32_t dst, const void* src) {
    asm volatile("cp.async.cg.shared.global [%0], [%1], 16;"
                 :: "r"(dst), "l"(src));
}
static __device__ __forceinline__ void cp_commit() {
    asm volatile("cp.async.commit_group;");
}
template<int NW> static __device__ __forceinline__ void cp_wait() {
    asm volatile("cp.async.wait_group %0;" :: "n"(NW));
}
static __device__ __forceinline__ void split1(float v, __nv_bfloat16& h, __nv_bfloat16& l) {
    h = __float2bfloat16(v);
    l = __float2bfloat16(v - __bfloat162float(h));
}
static __device__ __forceinline__ uint32_t pk2(__nv_bfloat16 a, __nv_bfloat16 b) {
    return (uint32_t)__bfloat16_as_ushort(a) | ((uint32_t)__bfloat16_as_ushort(b) << 16);
}
static __device__ __forceinline__ void split4v(float4 v, uint2& h, uint2& l) {
    __nv_bfloat16 h0,l0,h1,l1,h2,l2,h3,l3;
    split1(v.x,h0,l0); split1(v.y,h1,l1); split1(v.z,h2,l2); split1(v.w,h3,l3);
    h = make_uint2(pk2(h0,h1), pk2(h2,h3));
    l = make_uint2(pk2(l0,l1), pk2(l2,l3));
}
static __device__ __forceinline__ uint32_t swz64(int row, int u) {
    return (uint32_t)(row * 64 + ((u ^ ((row >> 1) & 3)) << 4));
}

// =====================================================================
// Fused prep: weight split + input patchnorm in ONE launch
// =====================================================================
__global__ void __launch_bounds__(256)
k_prep(const float* __restrict__ peW, const float* __restrict__ Win,
       const float* __restrict__ Wx,  const float* __restrict__ Wout,
       const float* __restrict__ x,   const float* __restrict__ in_g,
       const float* __restrict__ in_b)
{
    const int t0 = blockIdx.x * blockDim.x + threadIdx.x;
    const int stride = gridDim.x * blockDim.x;
    constexpr int T1 = NWIN / 4;
    constexpr int T2 = T1 + NWOUT / 4;
    constexpr int T3 = T2 + NWX / 4;

    for (int i4 = t0; i4 < T3; i4 += stride) {
        const float* src; __nv_bfloat16 *dh, *dl; int off;
        if (i4 < T1)      { src = Win;  dh = g_Winh;  dl = g_Winl;  off = i4; }
        else if (i4 < T2) { src = Wout; dh = g_Wouth; dl = g_Woutl; off = i4 - T1; }
        else              { src = Wx;   dh = g_Wxh;   dl = g_Wxl;   off = i4 - T2; }
        float4 v = *(const float4*)&src[(size_t)off * 4];
        uint2 h, l; split4v(v, h, l);
        *(uint2*)&dh[(size_t)off * 4] = h;
        *(uint2*)&dl[(size_t)off * 4] = l;
    }
    for (int i4 = t0; i4 < DMOD * (KPATCH / 4); i4 += stride) {
        int r = i4 / (KPATCH / 4), c4 = i4 % (KPATCH / 4);
        float4 v = *(const float4*)&peW[(size_t)r * KPATCH + c4 * 4];
        uint2 h, l; split4v(v, h, l);
        *(uint2*)&g_peWh[(size_t)r * KPPAD + c4 * 4] = h;
        *(uint2*)&g_peWl[(size_t)r * KPPAD + c4 * 4] = l;
    }
    for (int idx = t0; idx < BB * SEQLEN; idx += stride) {
        int b = idx / SEQLEN, s = idx % SEQLEN;
        const float* xp = x + idx * CINC;
        float sum = 0.f;
        #pragma unroll
        for (int c = 0; c < CINC; c++) sum += xp[c];
        float m = sum * (1.f / CINC);
        float var = 0.f;
        #pragma unroll
        for (int c = 0; c < CINC; c++) { float d = xp[c] - m; var = fmaf(d, d, var); }
        var *= (1.f / CINC);
        float inv = rsqrtf(var + 1e-5f);
        int n = s / PLEN, p = s % PLEN;
        size_t ro = (size_t)(b * NPATCH + n) * KPPAD;
        #pragma unroll
        for (int c = 0; c < CINC; c++) {
            float v = (xp[c] - m) * inv * in_g[c] + in_b[c];
            __nv_bfloat16 h, l; split1(v, h, l);
            g_pnh[ro + c * PLEN + p] = h;
            g_pnl[ro + c * PLEN + p] = l;
        }
    }
}

// =====================================================================
// bf16x3 mma.sync GEMM: swizzled SMEM, 3-stage cp.async.
// EPI: 0=store, 1=store+bias[n]
// =====================================================================
template<int BM, int BN, int EPI>
__global__ void __launch_bounds__(256, 2)
bgemm(int M, int N, int Ks,
      const __nv_bfloat16* __restrict__ Ah, const __nv_bfloat16* __restrict__ Al, int lda,
      const __nv_bfloat16* __restrict__ Wh, const __nv_bfloat16* __restrict__ Wl, int ldw,
      const float* __restrict__ bias, float* __restrict__ C, int ldc, int sliceC)
{
    constexpr int WNW = (BM == 128) ? 2 : 4;
    constexpr int WN  = BN / WNW;
    constexpr int NT8 = WN / 8;
    constexpr int APLB = BM * 64;
    constexpr int WPLB = BN * 64;
    constexpr int STGB = 2 * APLB + 2 * WPLB;

    extern __shared__ __nv_bfloat16 sm[];
    const uint32_t smu = smem_u32(sm);

    const int tid = threadIdx.x, lane = tid & 31, warp = tid >> 5;
    const int wn = warp % WNW, wm = warp / WNW;
    const int mB = blockIdx.y * BM, nB = blockIdx.x * BN;
    const int kbase = blockIdx.z * Ks;
    float* pC = C + (size_t)blockIdx.z * sliceC;

    float acc[2][NT8][4];
    #pragma unroll
    for (int t = 0; t < 2; t++)
        #pragma unroll
        for (int j = 0; j < NT8; j++)
            #pragma unroll
            for (int r = 0; r < 4; r++) acc[t][j][r] = 0.f;

    const int nCh = Ks / 32;

    auto load_stage = [&](int s) {
        const uint32_t sb = smu + (uint32_t)((s % 3) * STGB);
        const int k0 = kbase + s * 32;
        #pragma unroll
        for (int i = tid; i < BM * 4; i += 256) {
            int row = i >> 2, u = i & 3;
            size_t g = (size_t)(mB + row) * lda + k0 + u * 8;
            uint32_t d = sb + swz64(row, u);
            cp16(d, Ah + g);
            cp16(d + APLB, Al + g);
        }
        #pragma unroll
        for (int i = tid; i < BN * 4; i += 256) {
            int row = i >> 2, u = i & 3;
            size_t g = (size_t)(nB + row) * ldw + k0 + u * 8;
            uint32_t d = sb + 2 * APLB + swz64(row, u);
            cp16(d, Wh + g);
            cp16(d + WPLB, Wl + g);
        }
        cp_commit();
    };

    load_stage(0);
    if (nCh > 1) load_stage(1); else cp_commit();

    for (int s = 0; s < nCh; s++) {
        if (s + 2 < nCh) load_stage(s + 2); else cp_commit();
        cp_wait<2>();
        __syncthreads();

        const uint32_t sb = smu + (uint32_t)((s % 3) * STGB);
        #pragma unroll
        for (int k16 = 0; k16 < 2; k16++) {
            uint32_t ah[2][4], al[2][4], wf[NT8][2];
            const int arow = wm * 32 + (lane & 15);
            const int au   = k16 * 2 + (lane >> 4);
            const uint32_t aAddr = sb + swz64(arow, au);
            ldm_x4(ah[0], aAddr);
            ldm_x4(ah[1], aAddr + 16 * 64);

            const int wrow = wn * WN + ((lane >> 4) << 3) + (lane & 7);
            const int wu   = k16 * 2 + ((lane >> 3) & 1);
            const uint32_t wAddr = sb + 2 * APLB + swz64(wrow, wu);
            #pragma unroll
            for (int jp = 0; jp < NT8 / 2; jp++) {
                uint32_t t4[4];
                ldm_x4(t4, wAddr + jp * 16 * 64);
                wf[2*jp][0] = t4[0]; wf[2*jp][1] = t4[1];
                wf[2*jp+1][0] = t4[2]; wf[2*jp+1][1] = t4[3];
            }
            #pragma unroll
            for (int t = 0; t < 2; t++)
                #pragma unroll
                for (int j = 0; j < NT8; j++) mma_bf16(acc[t][j], ah[t], wf[j]);

            ldm_x4(al[0], aAddr + APLB);
            ldm_x4(al[1], aAddr + APLB + 16 * 64);
            #pragma unroll
            for (int t = 0; t < 2; t++)
                #pragma unroll
                for (int j = 0; j < NT8; j++) mma_bf16(acc[t][j], al[t], wf[j]);

            #pragma unroll
            for (int jp = 0; jp < NT8 / 2; jp++) {
                uint32_t t4[4];
                ldm_x4(t4, wAddr + WPLB + jp * 16 * 64);
                wf[2*jp][0] = t4[0]; wf[2*jp][1] = t4[1];
                wf[2*jp+1][0] = t4[2]; wf[2*jp+1][1] = t4[3];
            }
            #pragma unroll
            for (int t = 0; t < 2; t++)
                #pragma unroll
                for (int j = 0; j < NT8; j++) mma_bf16(acc[t][j], ah[t], wf[j]);
        }
        __syncthreads();
    }

    #pragma unroll
    for (int t = 0; t < 2; t++) {
        const int m = mB + wm * 32 + t * 16 + (lane >> 2);
        #pragma unroll
        for (int j = 0; j < NT8; j++) {
            const int n = nB + wn * WN + j * 8 + (lane & 3) * 2;
            float2 v0 = make_float2(acc[t][j][0], acc[t][j][1]);
            float2 v1 = make_float2(acc[t][j][2], acc[t][j][3]);
            if (EPI == 1) {
                float b0 = bias[n], b1 = bias[n + 1];
                v0.x += b0; v0.y += b1; v1.x += b0; v1.y += b1;
            }
            *(float2*)&pC[(size_t)m * ldc + n]       = v0;
            *(float2*)&pC[(size_t)(m + 8) * ldc + n] = v1;
        }
    }
}

// =====================================================================
// Warp-per-row layernorm (width 512) with optional fused W_out split-K
// residual accumulate: h = h + p0 + p1 (written back to hbuf).
// SPLIT=1: bf16 planes out; SPLIT=0: fp32 out.
// =====================================================================
template<int SPLIT>
__global__ void __launch_bounds__(256)
k_lnw(float* __restrict__ hbuf,
      const float* __restrict__ p0, const float* __restrict__ p1,
      float* __restrict__ outf,
      __nv_bfloat16* __restrict__ oh, __nv_bfloat16* __restrict__ ol,
      const float* __restrict__ gam, const float* __restrict__ bet)
{
    const int row  = blockIdx.x * 8 + (threadIdx.x >> 5);
    const int lane = threadIdx.x & 31;
    float* x = hbuf + (size_t)row * DMOD;

    float4 v[4];
    float s = 0.f, ss = 0.f;
    #pragma unroll
    for (int i = 0; i < 4; i++) {
        int c = i * 128 + lane * 4;
        v[i] = *(const float4*)&x[c];
        if (p0) {
            float4 a = *(const float4*)&p0[(size_t)row * DMOD + c];
            float4 b = *(const float4*)&p1[(size_t)row * DMOD + c];
            v[i].x += a.x + b.x; v[i].y += a.y + b.y;
            v[i].z += a.z + b.z; v[i].w += a.w + b.w;
            *(float4*)&x[c] = v[i];
        }
        s  += v[i].x + v[i].y + v[i].z + v[i].w;
        ss += v[i].x*v[i].x + v[i].y*v[i].y + v[i].z*v[i].z + v[i].w*v[i].w;
    }
    #pragma unroll
    for (int o = 16; o > 0; o >>= 1) {
        s  += __shfl_xor_sync(0xffffffffu, s,  o);
        ss += __shfl_xor_sync(0xffffffffu, ss, o);
    }
    float m   = s * (1.f / DMOD);
    float var = ss * (1.f / DMOD) - m * m;
    float inv = rsqrtf(var + 1e-5f);

    #pragma unroll
    for (int i = 0; i < 4; i++) {
        int c = i * 128 + lane * 4;
        float4 g = *(const float4*)&gam[c];
        float4 bb = *(const float4*)&bet[c];
        float o0 = (v[i].x - m) * inv * g.x + bb.x;
        float o1 = (v[i].y - m) * inv * g.y + bb.y;
        float o2 = (v[i].z - m) * inv * g.z + bb.z;
        float o3 = (v[i].w - m) * inv * g.w + bb.w;
        if (SPLIT) {
            float4 vv = make_float4(o0, o1, o2, o3);
            uint2 h, l; split4v(vv, h, l);
            size_t off = (size_t)row * DMOD + c;
            *(uint2*)&oh[off] = h;
            *(uint2*)&ol[off] = l;
        } else {
            *(float4*)&outf[(size_t)row * DMOD + c] = make_float4(o0, o1, o2, o3);
        }
    }
}

// =====================================================================
// Depthwise causal conv (DC=4) + silu, 2 channels/thread
// =====================================================================
__global__ void __launch_bounds__(256)
k_conv(const float* __restrict__ xz,
       const float* __restrict__ cw,
       const float* __restrict__ cb)
{
    int idx = blockIdx.x * blockDim.x + threadIdx.x;
    if (idx >= MROWS * DINNER / 2) return;
    int d2 = idx % (DINNER / 2);
    int bl = idx / (DINNER / 2);
    int d  = d2 * 2;
    int l  = bl % NPATCH;
    int b  = bl / NPATCH;
    const float4 w0 = *(const float4*)(cw + d * 4);
    const float4 w1 = *(const float4*)(cw + d * 4 + 4);
    float2 cbv = *(const float2*)(cb + d);
    float a0 = cbv.x, a1 = cbv.y;
    size_t base = (size_t)(b * NPATCH) * 2 * DINNER + d;
    float2 t;
    if (l >= 3) { t = *(const float2*)&xz[base + (size_t)(l-3)*2*DINNER];
                  a0 = fmaf(t.x, w0.x, a0); a1 = fmaf(t.y, w1.x, a1); }
    if (l >= 2) { t = *(const float2*)&xz[base + (size_t)(l-2)*2*DINNER];
                  a0 = fmaf(t.x, w0.y, a0); a1 = fmaf(t.y, w1.y, a1); }
    if (l >= 1) { t = *(const float2*)&xz[base + (size_t)(l-1)*2*DINNER];
                  a0 = fmaf(t.x, w0.z, a0); a1 = fmaf(t.y, w1.z, a1); }
    t = *(const float2*)&xz[base + (size_t)l*2*DINNER];
    a0 = fmaf(t.x, w0.w, a0); a1 = fmaf(t.y, w1.w, a1);
    float v0 = a0 / (1.f + __expf(-a0));
    float v1 = a1 / (1.f + __expf(-a1));
    __nv_bfloat16 h0, l0, h1, l1;
    split1(v0, h0, l0); split1(v1, h1, l1);
    size_t o = (size_t)bl * DINNER + d;
    *(uint32_t*)&g_xch[o] = pk2(h0, h1);
    *(uint32_t*)&g_xcl[o] = pk2(l0, l1);
}

// =====================================================================
// Selective scan v2: per-tile PARALLEL precompute of (q, delta), then a
// short-critical-path serial recurrence. Fused dbl split-K reduce.
// =====================================================================
__global__ void __launch_bounds__(128)
k_scan(const float* __restrict__ xz,  const float* __restrict__ dblp,
       const float* __restrict__ Wdt, const float* __restrict__ bdt,
       const float* __restrict__ A_log, const float* __restrict__ Dskip)
{
    const int tid  = threadIdx.x;
    const int ng   = tid & 3;
    const int dloc = tid >> 2;
    const int d    = blockIdx.x * 32 + dloc;
    const int b    = blockIdx.y;

    __shared__ float sdbl[16][68];
    __shared__ float swdt[32][33];
    __shared__ float sq [16][32];
    __shared__ float sdl[16][32];

    {
        int r = tid >> 2, c0 = (tid & 3) * 8;
        #pragma unroll
        for (int j = 0; j < 8; j++)
            swdt[r][c0 + j] = Wdt[(blockIdx.x * 32 + r) * DTRANK + c0 + j];
    }
    const float bv = bdt[d];

    float a[4];
    bool structured = true;
    #pragma unroll
    for (int i = 0; i < 4; i++) {
        int n = ng * 4 + i;
        a[i] = -__expf(A_log[d * NST + n]);
        structured = structured && (fabsf(a[i] + (float)(n + 1)) <= 1e-4f * (float)(n + 1));
    }
    const float Dv = Dskip[d];
    float h[4] = {0.f, 0.f, 0.f, 0.f};

    for (int tt = 0; tt < NPATCH; tt += 16) {
        __syncthreads();
        #pragma unroll
        for (int q8 = 0; q8 < 2; q8++) {
            int f4 = tid + q8 * 128;
            int r = f4 >> 4, c4 = f4 & 15;
            size_t gi = (size_t)(b * NPATCH + tt + r) * 64 + c4 * 4;
            float4 v0 = *(const float4*)&dblp[gi];
            float4 v1 = *(const float4*)&dblp[gi + (size_t)MROWS * 64];
            float4 v2 = *(const float4*)&dblp[gi + (size_t)2 * MROWS * 64];
            float4 v3 = *(const float4*)&dblp[gi + (size_t)3 * MROWS * 64];
            *(float4*)&sdbl[r][c4 * 4] = make_float4(
                v0.x + v1.x + v2.x + v3.x, v0.y + v1.y + v2.y + v3.y,
                v0.z + v1.z + v2.z + v3.z, v0.w + v1.w + v2.w + v3.w);
        }
        __syncthreads();

        #pragma unroll
        for (int tt2 = 0; tt2 < 4; tt2++) {
            int t2 = tt2 * 4 + ng;
            float d0 = bv, d1 = 0.f;
            #pragma unroll
            for (int j = 0; j < 16; j++) {
                d0 = fmaf(sdbl[t2][2*j],     swdt[dloc][2*j],     d0);
                d1 = fmaf(sdbl[t2][2*j + 1], swdt[dloc][2*j + 1], d1);
            }
            float xv = d0 + d1;
            float q, delta;
            if (xv > 0.f) {
                float e = __expf(-xv);
                q = e / (1.f + e);
                delta = xv + __logf(1.f + e);
            } else {
                float e = __expf(xv);
                q = 1.f / (1.f + e);
                delta = __logf(1.f + e);
            }
            sq [t2][dloc] = q;
            sdl[t2][dloc] = delta;
        }
        __syncthreads();

        const int row0 = b * NPATCH + tt;
        float xch_c = __bfloat162float(g_xch[(size_t)row0 * DINNER + d]);
        float xcl_c = __bfloat162float(g_xcl[(size_t)row0 * DINNER + d]);
        float zv_c  = xz[(size_t)row0 * 2 * DINNER + DINNER + d];

        #pragma unroll 4
        for (int t2 = 0; t2 < 16; t2++) {
            float xch_n = 0.f, xcl_n = 0.f, zv_n = 0.f;
            if (t2 < 15) {
                size_t r1 = (size_t)(row0 + t2 + 1);
                xch_n = __bfloat162float(g_xch[r1 * DINNER + d]);
                xcl_n = __bfloat162float(g_xcl[r1 * DINNER + d]);
                zv_n  = xz[r1 * 2 * DINNER + DINNER + d];
            }
            float q     = sq [t2][dloc];
            float delta = sdl[t2][dloc];

            float pw[4];
            if (structured) {
                float q2 = q * q, q4 = q2 * q2;
                float b1 = (ng & 1) ? q4 : 1.f;
                float b2 = (ng & 2) ? q4 * q4 : 1.f;
                float bs = b1 * b2;
                pw[0] = bs * q;      pw[1] = bs * q2;
                pw[2] = bs * q2 * q; pw[3] = bs * q4;
            } else {
                #pragma unroll
                for (int i = 0; i < 4; i++) pw[i] = __expf(delta * a[i]);
            }

            float xcv = xch_c + xcl_c;
            float dx = delta * xcv;
            float acc = 0.f;
            #pragma unroll
            for (int i = 0; i < 4; i++) {
                int n = ng * 4 + i;
                h[i] = fmaf(pw[i], h[i], dx * sdbl[t2][32 + n]);
                acc  = fmaf(h[i], sdbl[t2][48 + n], acc);
            }
            acc += __shfl_xor_sync(0xffffffffu, acc, 1);
            acc += __shfl_xor_sync(0xffffffffu, acc, 2);
            if (ng == 0) {
                float sz = zv_c / (1.f + __expf(-zv_c));
                float yv = (acc + xcv * Dv) * sz;
                __nv_bfloat16 hh, ll; split1(yv, hh, ll);
                size_t di = (size_t)(row0 + t2) * DINNER + d;
                g_yh[di] = hh; g_yl[di] = ll;
            }
            xch_c = xch_n; xcl_c = xcl_n; zv_c = zv_n;
        }
    }
}

// =====================================================================
// Head GEMM1: 256 split-K blocks, coalesced W staging
// =====================================================================
__global__ void __launch_bounds__(256)
k_head1(const float* __restrict__ hin, const float* __restrict__ W,
        float* __restrict__ part)
{
    const int z = blockIdx.x;
    const int kbase = z * (KFLAT / HKS);
    const int tid = threadIdx.x;
    const int j = tid & 127, g = tid >> 7;
    __shared__ float shw[128][65];
    __shared__ float shh[8][65];
    float acc[4] = {0.f, 0.f, 0.f, 0.f};

    for (int kc = 0; kc < KFLAT / HKS; kc += 64) {
        const int k0 = kbase + kc;
        #pragma unroll
        for (int i = tid; i < 128 * 16; i += 256) {
            int r = i >> 4, c4 = i & 15;
            float4 v = *(const float4*)&W[(size_t)r * KFLAT + k0 + c4 * 4];
            shw[r][c4*4+0] = v.x; shw[r][c4*4+1] = v.y;
            shw[r][c4*4+2] = v.z; shw[r][c4*4+3] = v.w;
        }
        if (tid < 128) {
            int r = tid >> 4, c4 = tid & 15;
            float4 v = *(const float4*)&hin[(size_t)r * KFLAT + k0 + c4 * 4];
            shh[r][c4*4+0] = v.x; shh[r][c4*4+1] = v.y;
            shh[r][c4*4+2] = v.z; shh[r][c4*4+3] = v.w;
        }
        __syncthreads();
        #pragma unroll 8
        for (int kk = 0; kk < 64; kk++) {
            float w = shw[j][kk];
            #pragma unroll
            for (int bq = 0; bq < 4; bq++)
                acc[bq] = fmaf(w, shh[g * 4 + bq][kk], acc[bq]);
        }
        __syncthreads();
    }
    #pragma unroll
    for (int bq = 0; bq < 4; bq++)
        part[(size_t)z * (BB * 128) + (g * 4 + bq) * 128 + j] = acc[bq];
}

__global__ void __launch_bounds__(128)
k_head2(const float* __restrict__ part, const float* __restrict__ hb1,
        const float* __restrict__ hW2,  const float* __restrict__ hb2,
        float* __restrict__ out)
{
    const int b = blockIdx.x;
    const int tid = threadIdx.x;
    __shared__ float g[128];
    float v = 0.f;
    for (int z = 0; z < HKS; z++)
        v += part[(size_t)z * (BB * 128) + b * 128 + tid];
    v += hb1[tid];
    g[tid] = 0.5f * v * (1.f + erff(v * 0.70710678118654752f));
    __syncthreads();
    if (tid < HPRED) {
        float acc = hb2[tid];
        #pragma unroll 16
        for (int j = 0; j < 128; j++)
            acc = fmaf(g[j], hW2[tid * 128 + j], acc);
        out[b * HPRED + tid] = acc;
    }
}

// =====================================================================
// Launch
// =====================================================================
static void* symaddr(const void* sym)
{
    void* p = nullptr;
    cudaGetSymbolAddress(&p, sym);
    return p;
}

#define STGBYTES(BM, BN) (2 * (BM) * 64 + 2 * (BN) * 64)
#define SMSZ(BM, BN) (3 * STGBYTES(BM, BN))

extern "C" void kernel_launch(void* const* d_in, const int* in_sizes, int n_in,
                              void* d_out, int out_size)
{
    const float* x      = (const float*)d_in[0];
    const float* in_g   = (const float*)d_in[1];
    const float* in_b   = (const float*)d_in[2];
    const float* pe_W   = (const float*)d_in[3];
    const float* pe_b   = (const float*)d_in[4];
    const float* ln_g   = (const float*)d_in[5];
    const float* ln_b   = (const float*)d_in[6];
    const float* W_in   = (const float*)d_in[7];
    const float* conv_W = (const float*)d_in[8];
    const float* conv_b = (const float*)d_in[9];
    const float* W_x    = (const float*)d_in[10];
    const float* W_dt   = (const float*)d_in[11];
    const float* b_dt   = (const float*)d_in[12];
    const float* A_log  = (const float*)d_in[13];
    const float* Dskip  = (const float*)d_in[14];
    const float* W_out  = (const float*)d_in[15];
    const float* fn_g   = (const float*)d_in[16];
    const float* fn_b   = (const float*)d_in[17];
    const float* hW1    = (const float*)d_in[18];
    const float* hb1    = (const float*)d_in[19];
    const float* hW2    = (const float*)d_in[20];
    const float* hb2    = (const float*)d_in[21];

    float* ph    = (float*)symaddr(g_h);
    float* pln   = (float*)symaddr(g_ln);
    float* pxz   = (float*)symaddr(g_xz);
    float* pdblp = (float*)symaddr(g_dblp);
    float* pwop  = (float*)symaddr(g_wop);
    float* ppart = (float*)symaddr(g_part);

    __nv_bfloat16* pnh = (__nv_bfloat16*)symaddr(g_pnh);
    __nv_bfloat16* pnl = (__nv_bfloat16*)symaddr(g_pnl);
    __nv_bfloat16* lnh = (__nv_bfloat16*)symaddr(g_lnh);
    __nv_bfloat16* lnl = (__nv_bfloat16*)symaddr(g_lnl);
    __nv_bfloat16* xch = (__nv_bfloat16*)symaddr(g_xch);
    __nv_bfloat16* xcl = (__nv_bfloat16*)symaddr(g_xcl);
    __nv_bfloat16* yh  = (__nv_bfloat16*)symaddr(g_yh);
    __nv_bfloat16* yl  = (__nv_bfloat16*)symaddr(g_yl);

    __nv_bfloat16* peWh = (__nv_bfloat16*)symaddr(g_peWh);
    __nv_bfloat16* peWl = (__nv_bfloat16*)symaddr(g_peWl);
    __nv_bfloat16* Winh = (__nv_bfloat16*)symaddr(g_Winh);
    __nv_bfloat16* Winl = (__nv_bfloat16*)symaddr(g_Winl);
    __nv_bfloat16* Wxh  = (__nv_bfloat16*)symaddr(g_Wxh);
    __nv_bfloat16* Wxl  = (__nv_bfloat16*)symaddr(g_Wxl);
    __nv_bfloat16* Wouth= (__nv_bfloat16*)symaddr(g_Wouth);
    __nv_bfloat16* Woutl= (__nv_bfloat16*)symaddr(g_Woutl);

    static bool attr_done = false;
    if (!attr_done) {
        cudaFuncSetAttribute(bgemm<128,128,0>, cudaFuncAttributeMaxDynamicSharedMemorySize, SMSZ(128,128));
        cudaFuncSetAttribute(bgemm<64,128,0>,  cudaFuncAttributeMaxDynamicSharedMemorySize, SMSZ(64,128));
        cudaFuncSetAttribute(bgemm<64,128,1>,  cudaFuncAttributeMaxDynamicSharedMemorySize, SMSZ(64,128));
        cudaFuncSetAttribute(bgemm<64,64,0>,   cudaFuncAttributeMaxDynamicSharedMemorySize, SMSZ(64,64));
        attr_done = true;
    }

    // 0) fused prep: weight split + input LN/patch planes
    k_prep<<<1024, 256>>>(pe_W, W_in, W_x, W_out, x, in_g, in_b);

    // 1) patch embed (2048x512, K=128 padded)
    bgemm<64,128,1><<<dim3(DMOD/128, MROWS/64), 256, SMSZ(64,128)>>>(
        MROWS, DMOD, KPPAD, pnh, pnl, KPPAD, peWh, peWl, KPPAD, pe_b, ph, DMOD, 0);

    // 2) Mamba layers
    const float* wp0 = nullptr; const float* wp1 = nullptr;
    for (int i = 0; i < NLAY; i++) {
        // LN (+ fused W_out split-K residual accumulate from previous layer)
        k_lnw<1><<<MROWS/8, 256>>>(ph, wp0, wp1, nullptr, lnh, lnl,
                                   ln_g + i * DMOD, ln_b + i * DMOD);

        // xz = ln @ W_in^T  (2048 x 2048, K=512)
        bgemm<128,128,0><<<dim3(2*DINNER/128, MROWS/128), 256, SMSZ(128,128)>>>(
            MROWS, 2*DINNER, DMOD, lnh, lnl, DMOD,
            Winh + (size_t)i*2*DINNER*DMOD, Winl + (size_t)i*2*DINNER*DMOD, DMOD,
            nullptr, pxz, 2*DINNER, 0);

        k_conv<<<(MROWS * DINNER / 2 + 255) / 256, 256>>>(
            pxz, conv_W + (size_t)i*DINNER*DCONV, conv_b + (size_t)i*DINNER);

        // dbl partial = xc @ W_x^T  (2048 x 64, K split 4 x 256)
        bgemm<64,64,0><<<dim3(1, MROWS/64, DBLKS), 256, SMSZ(64,64)>>>(
            MROWS, 64, DINNER/DBLKS, xch, xcl, DINNER,
            Wxh + (size_t)i*64*DINNER, Wxl + (size_t)i*64*DINNER, DINNER,
            nullptr, pdblp, 64, MROWS*64);

        // scan v2 (parallel q/delta precompute + fused partial reduce)
        k_scan<<<dim3(DINNER/32, BB), 128>>>(
            pxz, pdblp,
            W_dt + (size_t)i*DINNER*DTRANK, b_dt + (size_t)i*DINNER,
            A_log + (size_t)i*DINNER*NST, Dskip + (size_t)i*DINNER);

        // W_out partials: y @ W_out^T  (2048 x 512, K split 2 x 512): 256 CTAs
        bgemm<64,128,0><<<dim3(DMOD/128, MROWS/64, WOKS), 256, SMSZ(64,128)>>>(
            MROWS, DMOD, DINNER/WOKS, yh, yl, DINNER,
            Wouth + (size_t)i*DMOD*DINNER, Woutl + (size_t)i*DMOD*DINNER, DINNER,
            nullptr, pwop, DMOD, MROWS*DMOD);
        wp0 = pwop; wp1 = pwop + (size_t)MROWS * DMOD;
    }

    // 3) final LN (fused last W_out accumulate; fp32 out for head)
    k_lnw<0><<<MROWS/8, 256>>>(ph, wp0, wp1, pln, nullptr, nullptr, fn_g, fn_b);

    // 4) head
    k_head1<<<HKS, 256>>>(pln, hW1, ppart);
    k_head2<<<BB, 128>>>(ppart, hb1, hW2, hb2, (float*)d_out);
}